// round 14
// baseline (speedup 1.0000x reference)
#include <cuda_runtime.h>
#include <cuda_bf16.h>
#include <math.h>
#include <cstdint>

// ---------------- problem constants ----------------
#define L_       4096
#define HIDD     2048
#define Hh       64
#define Pp       64
#define Nn       128
#define CHh      256
#define NC       16
#define INTER    4096
#define CONV_DIM 4352            // INTER + 2N
#define OUT_IN   8512            // 2*(INTER+N) + H
#define OUT_IN_PAD 8576          // 67 * 128
#define XBC_OFF  INTER
#define DTRAW_OFF (2*INTER + 2*Nn)

// ---------------- device scratch (static; no runtime alloc) ----------------
__device__ float g_zx[L_ * OUT_IN];
__device__ float g_x[L_ * INTER];
__device__ float g_dt[NC * Hh * CHh];
__device__ float g_acs[NC * Hh * CHh];
__device__ float g_states[NC * Hh * Pp * Nn];
__device__ float g_y[L_ * INTER];

__device__ __nv_bfloat16 gA1h[L_ * HIDD];
__device__ __nv_bfloat16 gA1l[L_ * HIDD];
__device__ __nv_bfloat16 gB1h[OUT_IN_PAD * HIDD];
__device__ __nv_bfloat16 gB1l[OUT_IN_PAD * HIDD];
__device__ __nv_bfloat16 gA2h[L_ * INTER];
__device__ __nv_bfloat16 gA2l[L_ * INTER];
__device__ __nv_bfloat16 gB2h[HIDD * INTER];
__device__ __nv_bfloat16 gB2l[HIDD * INTER];

__device__ __nv_bfloat16 g_xdth[L_ * INTER];
__device__ __nv_bfloat16 g_xdtl[L_ * INTER];
__device__ __nv_bfloat16 g_bch[L_ * 256];
__device__ __nv_bfloat16 g_bcl[L_ * 256];
__device__ __nv_bfloat16 g_stinh[NC * Hh * Pp * Nn];
__device__ __nv_bfloat16 g_stinl[NC * Hh * Pp * Nn];

// ================= low-level helpers =================
__device__ __forceinline__ uint32_t smem_u32(const void* p) {
    uint32_t a;
    asm("{ .reg .u64 t; cvta.to.shared.u64 t, %1; cvt.u32.u64 %0, t; }" : "=r"(a) : "l"(p));
    return a;
}
#define CP16(sm, gm) \
    asm volatile("cp.async.cg.shared.global [%0], [%1], 16;" :: "r"(sm), "l"(gm) : "memory")
#define CP_COMMIT() asm volatile("cp.async.commit_group;" ::: "memory")
#define CP_WAIT(n)  asm volatile("cp.async.wait_group %0;" :: "n"(n) : "memory")

__device__ __forceinline__ void ldsm_x4(uint32_t& r0, uint32_t& r1, uint32_t& r2, uint32_t& r3,
                                        uint32_t addr) {
    asm volatile("ldmatrix.sync.aligned.m8n8.x4.shared.b16 {%0,%1,%2,%3}, [%4];"
                 : "=r"(r0), "=r"(r1), "=r"(r2), "=r"(r3) : "r"(addr));
}
__device__ __forceinline__ void ldsm_x4_t(uint32_t& r0, uint32_t& r1, uint32_t& r2, uint32_t& r3,
                                          uint32_t addr) {
    asm volatile("ldmatrix.sync.aligned.m8n8.x4.trans.shared.b16 {%0,%1,%2,%3}, [%4];"
                 : "=r"(r0), "=r"(r1), "=r"(r2), "=r"(r3) : "r"(addr));
}
__device__ __forceinline__ void mma16816(float* d, const uint32_t* a, uint32_t b0, uint32_t b1) {
    asm volatile("mma.sync.aligned.m16n8k16.row.col.f32.bf16.bf16.f32 "
                 "{%0,%1,%2,%3}, {%4,%5,%6,%7}, {%8,%9}, {%0,%1,%2,%3};"
                 : "+f"(d[0]), "+f"(d[1]), "+f"(d[2]), "+f"(d[3])
                 : "r"(a[0]), "r"(a[1]), "r"(a[2]), "r"(a[3]), "r"(b0), "r"(b1));
}
__device__ __forceinline__ uint32_t pk(__nv_bfloat16 a, __nv_bfloat16 b) {
    __nv_bfloat162 t; t.x = a; t.y = b;
    return *reinterpret_cast<uint32_t*>(&t);
}
__device__ __forceinline__ void split2(float x, __nv_bfloat16& h, __nv_bfloat16& l) {
    h = __float2bfloat16(x);
    l = __float2bfloat16(x - __bfloat162float(h));
}

// ================= split / transpose conversion kernels =================
__global__ void split_kernel(const float* __restrict__ in, __nv_bfloat16* __restrict__ hi,
                             __nv_bfloat16* __restrict__ lo, int n4) {
    int i = blockIdx.x * 256 + threadIdx.x;
    if (i >= n4) return;
    float4 v = ((const float4*)in)[i];
    __nv_bfloat16 h0, h1, h2, h3, l0, l1, l2, l3;
    split2(v.x, h0, l0); split2(v.y, h1, l1); split2(v.z, h2, l2); split2(v.w, h3, l3);
    ((uint2*)hi)[i] = make_uint2(pk(h0, h1), pk(h2, h3));
    ((uint2*)lo)[i] = make_uint2(pk(l0, l1), pk(l2, l3));
}

__global__ void transpose_split_kernel(const float* __restrict__ W,
                                       __nv_bfloat16* __restrict__ outH,
                                       __nv_bfloat16* __restrict__ outL,
                                       int K, int N) {
    __shared__ float tile[32][33];
    int n0 = blockIdx.x * 32, k0 = blockIdx.y * 32;
    int tx = threadIdx.x, ty = threadIdx.y;
#pragma unroll
    for (int i = 0; i < 4; i++) {
        int k = k0 + ty + i * 8;
        int n = n0 + tx;
        tile[ty + i * 8][tx] = (n < N) ? W[(size_t)k * N + n] : 0.f;
    }
    __syncthreads();
#pragma unroll
    for (int i = 0; i < 4; i++) {
        int nrow = n0 + ty + i * 8;
        int kcol = k0 + tx;
        float x = tile[tx][ty + i * 8];
        __nv_bfloat16 h, l;
        split2(x, h, l);
        outH[(size_t)nrow * K + kcol] = h;
        outL[(size_t)nrow * K + kcol] = l;
    }
}

// ================= HMMA split-bf16 GEMM: packed hi/lo rows, 5 stages =================
// Inner loop: product-major (nt inside) so same-acc RAW chains are 4 MMAs apart.
#define KT      16
#define PITCHB  80
#define PARR_B  (128 * PITCHB)
#define STAGE_B (2 * PARR_B)
#define NSTG    5

extern __shared__ __align__(128) char gsm_raw[];

__global__ void __launch_bounds__(256, 2)
gemm_hmma(const __nv_bfloat16* __restrict__ Ah, const __nv_bfloat16* __restrict__ Al,
          const __nv_bfloat16* __restrict__ Bh, const __nv_bfloat16* __restrict__ Bl,
          float* __restrict__ C, int Nreal, int K) {
    const int tid = threadIdx.x;
    const int lane = tid & 31, wid = tid >> 5;
    const int wm = wid & 1, wn = wid >> 1;
    const int row0 = blockIdx.y * 128, col0 = blockIdx.x * 128;
    const uint32_t sb = smem_u32(gsm_raw);

    const int lrow = tid >> 1;
    const int lelem = (tid & 1) * 8;
    const __nv_bfloat16* pAh = Ah + (size_t)(row0 + lrow) * K + lelem;
    const __nv_bfloat16* pAl = Al + (size_t)(row0 + lrow) * K + lelem;
    const __nv_bfloat16* pBh = Bh + (size_t)(col0 + lrow) * K + lelem;
    const __nv_bfloat16* pBl = Bl + (size_t)(col0 + lrow) * K + lelem;
    const uint32_t dstA = lrow * PITCHB + (tid & 1) * 16;

    float acc[4][4][4];
#pragma unroll
    for (int m = 0; m < 4; m++)
#pragma unroll
        for (int n = 0; n < 4; n++)
#pragma unroll
            for (int v = 0; v < 4; v++) acc[m][n][v] = 0.f;

    const int T = K / KT;

#define GFILL_NC(sidx, ko) do { \
        uint32_t _s = sb + (sidx) * STAGE_B; \
        CP16(_s + dstA,               pAh + (ko)); \
        CP16(_s + dstA + 32,          pAl + (ko)); \
        CP16(_s + PARR_B + dstA,      pBh + (ko)); \
        CP16(_s + PARR_B + dstA + 32, pBl + (ko)); \
    } while (0)

#pragma unroll
    for (int t = 0; t < 4; t++) {
        GFILL_NC(t, t * KT);
        CP_COMMIT();
    }

    const uint32_t a_frag_base = (wm * 64 + (lane & 15)) * PITCHB + (lane >> 4) * 16;
    const uint32_t b_frag_base = (wn * 32 + (lane & 7) + (lane >> 4) * 8) * PITCHB
                                 + ((lane >> 3) & 1) * 16;

    int sread = 0, sfill = 4;
    for (int t = 0; t < T; t++) {
        CP_WAIT(2);
        __syncthreads();
        if (t + 4 < T) GFILL_NC(sfill, (t + 4) * KT);
        CP_COMMIT();

        const uint32_t st = sb + sread * STAGE_B;
        uint32_t bh[2][4], bl[2][4];
#pragma unroll
        for (int np = 0; np < 2; np++) {
            uint32_t bo = st + PARR_B + b_frag_base + np * (16 * PITCHB);
            ldsm_x4(bh[np][0], bh[np][1], bh[np][2], bh[np][3], bo);
            ldsm_x4(bl[np][0], bl[np][1], bl[np][2], bl[np][3], bo + 32);
        }
#pragma unroll
        for (int mt = 0; mt < 4; mt++) {
            uint32_t ah[4], al[4];
            uint32_t ao = st + a_frag_base + mt * (16 * PITCHB);
            ldsm_x4(ah[0], ah[1], ah[2], ah[3], ao);
            ldsm_x4(al[0], al[1], al[2], al[3], ao + 32);
            // product-major: same-acc reuse distance = 4 MMAs; per-acc order hh,hl,lh preserved
#pragma unroll
            for (int nt = 0; nt < 4; nt++) {
                int np = nt >> 1, hv = (nt & 1) * 2;
                mma16816(acc[mt][nt], ah, bh[np][hv], bh[np][hv + 1]);
            }
#pragma unroll
            for (int nt = 0; nt < 4; nt++) {
                int np = nt >> 1, hv = (nt & 1) * 2;
                mma16816(acc[mt][nt], ah, bl[np][hv], bl[np][hv + 1]);
            }
#pragma unroll
            for (int nt = 0; nt < 4; nt++) {
                int np = nt >> 1, hv = (nt & 1) * 2;
                mma16816(acc[mt][nt], al, bh[np][hv], bh[np][hv + 1]);
            }
        }
        sread = (sread + 1 == NSTG) ? 0 : sread + 1;
        sfill = (sfill + 1 == NSTG) ? 0 : sfill + 1;
    }

#pragma unroll
    for (int mt = 0; mt < 4; mt++) {
        int r = row0 + wm * 64 + mt * 16 + (lane >> 2);
#pragma unroll
        for (int nt = 0; nt < 4; nt++) {
            int c = col0 + wn * 32 + nt * 8 + (lane & 3) * 2;
            if (c < Nreal) {
                *(float2*)&C[(size_t)r * Nreal + c]       = make_float2(acc[mt][nt][0], acc[mt][nt][1]);
                *(float2*)&C[(size_t)(r + 8) * Nreal + c] = make_float2(acc[mt][nt][2], acc[mt][nt][3]);
            }
        }
    }
#undef GFILL_NC
}

// ---------------- dt (softplus+clip) and per-chunk cumsum of dt*A ----------------
__global__ void dtcs_kernel(const float* __restrict__ dt_bias, const float* __restrict__ A_log) {
    int c = blockIdx.x, h = blockIdx.y;
    int t = threadIdx.x;
    int Lg = c * CHh + t;
    float raw = g_zx[(size_t)Lg * OUT_IN + DTRAW_OFF + h] + dt_bias[h];
    float sp = (raw > 20.f) ? raw : log1pf(expf(raw));
    float dt = fminf(fmaxf(sp, 0.f), 100.f);
    float A = -expf(A_log[h]);
    __shared__ float s[256];
    s[t] = dt * A;
    __syncthreads();
    for (int off = 1; off < 256; off <<= 1) {
        float v = (t >= off) ? s[t - off] : 0.f;
        __syncthreads();
        s[t] += v;
        __syncthreads();
    }
    int base = (c * Hh + h) * CHh;
    g_dt[base + t] = dt;
    g_acs[base + t] = s[t];
}

// ---------------- fused: causal conv + silu + xdt/BC bf16 split ----------------
__global__ void conv_fused_kernel(const float* __restrict__ cw, const float* __restrict__ cb) {
    int c = blockIdx.x * 256 + threadIdx.x;
    int l = blockIdx.y;
    float acc = cb[c];
#pragma unroll
    for (int k = 0; k < 4; k++) {
        int ll = l + k - 3;
        if (ll >= 0) acc = fmaf(g_zx[(size_t)ll * OUT_IN + XBC_OFF + c], cw[k * CONV_DIM + c], acc);
    }
    float s = acc / (1.f + expf(-acc));
    if (c < INTER) {
        int h = c >> 6;
        float dtv = g_dt[((l >> 8) * Hh + h) * CHh + (l & 255)];
        g_x[(size_t)l * INTER + c] = s;
        __nv_bfloat16 hh, ll2;
        split2(s * dtv, hh, ll2);
        g_xdth[(size_t)l * INTER + c] = hh;
        g_xdtl[(size_t)l * INTER + c] = ll2;
    } else {
        int cc = c - INTER;
        __nv_bfloat16 hh, ll2;
        split2(s, hh, ll2);
        g_bch[(size_t)l * 256 + cc] = hh;
        g_bcl[(size_t)l * 256 + cc] = ll2;
    }
}

// ---------------- HMMA states (cp.async B staging overlapped with X' compute) ----------------
extern __shared__ __align__(128) char ssm2[];
__global__ void __launch_bounds__(128, 2)
states_hmma() {
    const uint32_t sb = smem_u32(ssm2);
    const int tid = threadIdx.x, lane = tid & 31, w = tid >> 5;
    const int c = blockIdx.x, h = blockIdx.y;
    const int base = (c * Hh + h) * CHh;
    const float aend = g_acs[base + 255];
    float* wb = (float*)(ssm2 + 53248);
    for (int t = tid; t < 256; t += 128) wb[t] = expf(aend - g_acs[base + t]);

    float sacc[16][4];
#pragma unroll
    for (int j = 0; j < 16; j++)
#pragma unroll
        for (int v = 0; v < 4; v++) sacc[j][v] = 0.f;

    const uint32_t axb = sb + ((lane & 7) + (lane >> 4) * 8) * 144 + 32 * w + ((lane >> 3) & 1) * 16;
    const uint32_t bxb = sb + 18432 + ((lane & 7) + ((lane >> 3) & 1) * 8) * 272 + (lane >> 4) * 16;

    for (int kt = 0; kt < 4; kt++) {
        __syncthreads();
        int l0 = kt * 64;
        for (int e = tid; e < 1024; e += 128) {
            int row = e >> 4, s = e & 15;
            int lg = c * CHh + l0 + row;
            CP16(sb + 18432 + row * 272 + s * 16, &g_bch[(size_t)lg * 256 + s * 8]);
            CP16(sb + 35840 + row * 272 + s * 16, &g_bcl[(size_t)lg * 256 + s * 8]);
        }
        CP_COMMIT();
        for (int e = tid; e < 2048; e += 128) {
            int row = e >> 5, seg = e & 31;
            int lg = c * CHh + l0 + row;
            __nv_bfloat162 xh2 = *(const __nv_bfloat162*)&g_xdth[(size_t)lg * INTER + h * 64 + seg * 2];
            __nv_bfloat162 xl2 = *(const __nv_bfloat162*)&g_xdtl[(size_t)lg * INTER + h * 64 + seg * 2];
            float wv = wb[l0 + row];
            float v0 = (__bfloat162float(xh2.x) + __bfloat162float(xl2.x)) * wv;
            float v1 = (__bfloat162float(xh2.y) + __bfloat162float(xl2.y)) * wv;
            __nv_bfloat16 a0, a1, b0, b1;
            split2(v0, a0, b0); split2(v1, a1, b1);
            *(uint32_t*)(ssm2 + row * 144 + seg * 4) = pk(a0, a1);
            *(uint32_t*)(ssm2 + 9216 + row * 144 + seg * 4) = pk(b0, b1);
        }
        CP_WAIT(0);
        __syncthreads();

#pragma unroll
        for (int t = 0; t < 4; t++) {
            uint32_t ah[4], al[4];
            ldsm_x4_t(ah[0], ah[1], ah[2], ah[3], axb + t * 2304);
            ldsm_x4_t(al[0], al[1], al[2], al[3], axb + 9216 + t * 2304);
#pragma unroll
            for (int np = 0; np < 8; np++) {
                uint32_t bh[4], bl[4];
                ldsm_x4_t(bh[0], bh[1], bh[2], bh[3], bxb + t * 4352 + np * 32);
                ldsm_x4_t(bl[0], bl[1], bl[2], bl[3], bxb + 17408 + t * 4352 + np * 32);
                mma16816(sacc[2 * np],     ah, bh[0], bh[1]);
                mma16816(sacc[2 * np + 1], ah, bh[2], bh[3]);
                mma16816(sacc[2 * np],     ah, bl[0], bl[1]);
                mma16816(sacc[2 * np + 1], ah, bl[2], bl[3]);
                mma16816(sacc[2 * np],     al, bh[0], bh[1]);
                mma16816(sacc[2 * np + 1], al, bh[2], bh[3]);
            }
        }
    }

    float* out = g_states + (size_t)(c * Hh + h) * 8192;
    int p0 = 16 * w + (lane >> 2);
#pragma unroll
    for (int j = 0; j < 16; j++) {
        int n = 8 * j + 2 * (lane & 3);
        *(float2*)&out[p0 * 128 + n]       = make_float2(sacc[j][0], sacc[j][1]);
        *(float2*)&out[(p0 + 8) * 128 + n] = make_float2(sacc[j][2], sacc[j][3]);
    }
}

// ---------------- inter-chunk state scan (emits split stin) ----------------
__global__ void scan_kernel() {
    int idx = blockIdx.x * 256 + threadIdx.x;
    int h = idx >> 13;
    int rem = idx & 8191;
    float st = 0.f;
    for (int c = 0; c < NC; c++) {
        size_t o = (size_t)(c * Hh + h) * 8192 + rem;
        __nv_bfloat16 hi, lo;
        split2(st, hi, lo);
        g_stinh[o] = hi;
        g_stinl[o] = lo;
        float cend = g_acs[(c * Hh + h) * CHh + 255];
        st = st * expf(cend) + g_states[o];
    }
}

// ---------------- HMMA fused Y kernel: head-paired, shared C/B + raw-G reuse ----------------
#define OFF_CL   17408
#define OFF_UH   34816
#define OFF_UL   52224
#define OFF_X0H  69632
#define OFF_X0L  78848
#define OFF_X1H  88064
#define OFF_X1L  97280
#define OFF_AL0  106496
#define OFF_AL1  106752
#define OFF_AS0  107008
#define OFF_AS1  107264
#define YSMEM2   107520
extern __shared__ __align__(128) char ysm2[];
__global__ void __launch_bounds__(128, 2)
y_hmma(const float* __restrict__ Dv) {
    const uint32_t sb = smem_u32(ysm2);
    const int tid = threadIdx.x, lane = tid & 31, w = tid >> 5;
    const int lt = blockIdx.x, c = blockIdx.y, hp = blockIdx.z;
    const int h0 = 2 * hp, h1 = 2 * hp + 1;
    const int base0 = (c * Hh + h0) * CHh;
    const int base1 = (c * Hh + h1) * CHh;
    const int Lrow0 = c * CHh + lt * 64;
    float* acsl0 = (float*)(ysm2 + OFF_AL0);
    float* acsl1 = (float*)(ysm2 + OFF_AL1);
    float* acss0 = (float*)(ysm2 + OFF_AS0);
    float* acss1 = (float*)(ysm2 + OFF_AS1);

    const uint32_t a_base = sb + (16 * w + (lane & 15)) * 272 + (lane >> 4) * 16;
    const uint32_t b_base = sb + OFF_UH + ((lane & 7) + (lane >> 4) * 8) * 272 + ((lane >> 3) & 1) * 16;
    const uint32_t x0_base = sb + OFF_X0H + ((lane & 7) + ((lane >> 3) & 1) * 8) * 144 + (lane >> 4) * 16;
    const uint32_t x1_base = sb + OFF_X1H + ((lane & 7) + ((lane >> 3) & 1) * 8) * 144 + (lane >> 4) * 16;

    float yacc0[8][4], yacc1[8][4];
#pragma unroll
    for (int j = 0; j < 8; j++)
#pragma unroll
        for (int v = 0; v < 4; v++) { yacc0[j][v] = 0.f; yacc1[j][v] = 0.f; }

    // stage 1: C tile (shared) + Sin_h0
    {
        const size_t sinb0 = (size_t)(c * Hh + h0) * 8192;
        for (int e = tid; e < 1024; e += 128) {
            int row = e >> 4, s = e & 15;
            CP16(sb + row * 272 + s * 16,          &g_bch[(size_t)(Lrow0 + row) * 256 + 128 + s * 8]);
            CP16(sb + OFF_CL + row * 272 + s * 16, &g_bcl[(size_t)(Lrow0 + row) * 256 + 128 + s * 8]);
            CP16(sb + OFF_UH + row * 272 + s * 16, &g_stinh[sinb0 + row * 128 + s * 8]);
            CP16(sb + OFF_UL + row * 272 + s * 16, &g_stinl[sinb0 + row * 128 + s * 8]);
        }
        if (tid < 64) { acsl0[tid] = g_acs[base0 + lt * 64 + tid]; acsl1[tid] = g_acs[base1 + lt * 64 + tid]; }
        CP_COMMIT();
        CP_WAIT(0);
    }
    __syncthreads();

    // Y_off h0 = C . Sin0^T, scaled
#pragma unroll
    for (int kk = 0; kk < 8; kk++) {
        uint32_t ah[4], al[4];
        ldsm_x4(ah[0], ah[1], ah[2], ah[3], a_base + kk * 32);
        ldsm_x4(al[0], al[1], al[2], al[3], a_base + OFF_CL + kk * 32);
#pragma unroll
        for (int np = 0; np < 4; np++) {
            uint32_t bh[4], bl[4];
            ldsm_x4(bh[0], bh[1], bh[2], bh[3], b_base + np * 4352 + kk * 32);
            ldsm_x4(bl[0], bl[1], bl[2], bl[3], b_base + 17408 + np * 4352 + kk * 32);
            mma16816(yacc0[2 * np],     ah, bh[0], bh[1]);
            mma16816(yacc0[2 * np + 1], ah, bh[2], bh[3]);
            mma16816(yacc0[2 * np],     ah, bl[0], bl[1]);
            mma16816(yacc0[2 * np + 1], ah, bl[2], bl[3]);
            mma16816(yacc0[2 * np],     al, bh[0], bh[1]);
            mma16816(yacc0[2 * np + 1], al, bh[2], bh[3]);
        }
    }
    {
        float e0 = expf(acsl0[16 * w + (lane >> 2)]);
        float e1 = expf(acsl0[16 * w + (lane >> 2) + 8]);
#pragma unroll
        for (int j = 0; j < 8; j++) {
            yacc0[j][0] *= e0; yacc0[j][1] *= e0;
            yacc0[j][2] *= e1; yacc0[j][3] *= e1;
        }
    }

    // stage Sin_h1, then Y_off h1
    __syncthreads();
    {
        const size_t sinb1 = (size_t)(c * Hh + h1) * 8192;
        for (int e = tid; e < 1024; e += 128) {
            int row = e >> 4, s = e & 15;
            CP16(sb + OFF_UH + row * 272 + s * 16, &g_stinh[sinb1 + row * 128 + s * 8]);
            CP16(sb + OFF_UL + row * 272 + s * 16, &g_stinl[sinb1 + row * 128 + s * 8]);
        }
        CP_COMMIT();
        CP_WAIT(0);
    }
    __syncthreads();
#pragma unroll
    for (int kk = 0; kk < 8; kk++) {
        uint32_t ah[4], al[4];
        ldsm_x4(ah[0], ah[1], ah[2], ah[3], a_base + kk * 32);
        ldsm_x4(al[0], al[1], al[2], al[3], a_base + OFF_CL + kk * 32);
#pragma unroll
        for (int np = 0; np < 4; np++) {
            uint32_t bh[4], bl[4];
            ldsm_x4(bh[0], bh[1], bh[2], bh[3], b_base + np * 4352 + kk * 32);
            ldsm_x4(bl[0], bl[1], bl[2], bl[3], b_base + 17408 + np * 4352 + kk * 32);
            mma16816(yacc1[2 * np],     ah, bh[0], bh[1]);
            mma16816(yacc1[2 * np + 1], ah, bh[2], bh[3]);
            mma16816(yacc1[2 * np],     ah, bl[0], bl[1]);
            mma16816(yacc1[2 * np + 1], ah, bl[2], bl[3]);
            mma16816(yacc1[2 * np],     al, bh[0], bh[1]);
            mma16816(yacc1[2 * np + 1], al, bh[2], bh[3]);
        }
    }
    {
        float e0 = expf(acsl1[16 * w + (lane >> 2)]);
        float e1 = expf(acsl1[16 * w + (lane >> 2) + 8]);
#pragma unroll
        for (int j = 0; j < 8; j++) {
            yacc1[j][0] *= e0; yacc1[j][1] *= e0;
            yacc1[j][2] *= e1; yacc1[j][3] *= e1;
        }
    }

    const int l0row = 16 * w + (lane >> 2);

    for (int st = 0; st <= lt; st++) {
        const int Srow0 = c * CHh + st * 64;
        __syncthreads();
        for (int e = tid; e < 1024; e += 128) {
            int row = e >> 4, s = e & 15;
            CP16(sb + OFF_UH + row * 272 + s * 16, &g_bch[(size_t)(Srow0 + row) * 256 + s * 8]);
            CP16(sb + OFF_UL + row * 272 + s * 16, &g_bcl[(size_t)(Srow0 + row) * 256 + s * 8]);
        }
        for (int e = tid; e < 512; e += 128) {
            int row = e >> 3, s = e & 7;
            CP16(sb + OFF_X0H + row * 144 + s * 16, &g_xdth[(size_t)(Srow0 + row) * INTER + h0 * 64 + s * 8]);
            CP16(sb + OFF_X0L + row * 144 + s * 16, &g_xdtl[(size_t)(Srow0 + row) * INTER + h0 * 64 + s * 8]);
            CP16(sb + OFF_X1H + row * 144 + s * 16, &g_xdth[(size_t)(Srow0 + row) * INTER + h1 * 64 + s * 8]);
            CP16(sb + OFF_X1L + row * 144 + s * 16, &g_xdtl[(size_t)(Srow0 + row) * INTER + h1 * 64 + s * 8]);
        }
        if (tid < 64) { acss0[tid] = g_acs[base0 + st * 64 + tid]; acss1[tid] = g_acs[base1 + st * 64 + tid]; }
        CP_COMMIT();
        CP_WAIT(0);
        __syncthreads();

        // raw G = C . B^T (shared across both heads)
        float gacc[8][4];
#pragma unroll
        for (int j = 0; j < 8; j++)
#pragma unroll
            for (int v = 0; v < 4; v++) gacc[j][v] = 0.f;
#pragma unroll
        for (int kk = 0; kk < 8; kk++) {
            uint32_t ah[4], al[4];
            ldsm_x4(ah[0], ah[1], ah[2], ah[3], a_base + kk * 32);
            ldsm_x4(al[0], al[1], al[2], al[3], a_base + OFF_CL + kk * 32);
#pragma unroll
            for (int np = 0; np < 4; np++) {
                uint32_t bh[4], bl[4];
                ldsm_x4(bh[0], bh[1], bh[2], bh[3], b_base + np * 4352 + kk * 32);
                ldsm_x4(bl[0], bl[1], bl[2], bl[3], b_base + 17408 + np * 4352 + kk * 32);
                mma16816(gacc[2 * np],     ah, bh[0], bh[1]);
                mma16816(gacc[2 * np + 1], ah, bh[2], bh[3]);
                mma16816(gacc[2 * np],     ah, bl[0], bl[1]);
                mma16816(gacc[2 * np + 1], ah, bl[2], bl[3]);
                mma16816(gacc[2 * np],     al, bh[0], bh[1]);
                mma16816(gacc[2 * np + 1], al, bh[2], bh[3]);
            }
        }

        const bool diag = (st == lt);
        // per-head: decay applied during split (gacc preserved), then GX MMA
#pragma unroll
        for (int hh = 0; hh < 2; hh++) {
            const float* acslh = hh ? acsl1 : acsl0;
            const float* acssh = hh ? acss1 : acss0;
            const uint32_t xb = hh ? x1_base : x0_base;
            float (*yh)[4] = hh ? yacc1 : yacc0;
            float rA = acslh[l0row];
            float rB = acslh[l0row + 8];
#pragma unroll
            for (int t = 0; t < 4; t++) {
                uint32_t gah[4], gal[4];
#pragma unroll
                for (int half = 0; half < 2; half++) {
                    int j = 2 * t + half;
                    int s0 = 8 * j + 2 * (lane & 3);
                    float c0 = acssh[s0], c1 = acssh[s0 + 1];
                    float e00 = expf(rA - c0), e01 = expf(rA - c1);
                    float e10 = expf(rB - c0), e11 = expf(rB - c1);
                    if (diag) {
                        if (s0 > l0row)         e00 = 0.f;
                        if (s0 + 1 > l0row)     e01 = 0.f;
                        if (s0 > l0row + 8)     e10 = 0.f;
                        if (s0 + 1 > l0row + 8) e11 = 0.f;
                    }
                    float v0 = gacc[j][0] * e00, v1 = gacc[j][1] * e01;
                    float v2 = gacc[j][2] * e10, v3 = gacc[j][3] * e11;
                    __nv_bfloat16 p0, p1, p2, p3, q0, q1, q2, q3;
                    split2(v0, p0, q0); split2(v1, p1, q1);
                    split2(v2, p2, q2); split2(v3, p3, q3);
                    gah[2 * half]     = pk(p0, p1);
                    gah[2 * half + 1] = pk(p2, p3);
                    gal[2 * half]     = pk(q0, q1);
                    gal[2 * half + 1] = pk(q2, q3);
                }
#pragma unroll
                for (int np = 0; np < 4; np++) {
                    uint32_t xh[4], xl[4];
                    ldsm_x4_t(xh[0], xh[1], xh[2], xh[3], xb + t * 2304 + np * 32);
                    ldsm_x4_t(xl[0], xl[1], xl[2], xl[3], xb + 9216 + t * 2304 + np * 32);
                    mma16816(yh[2 * np],     gah, xh[0], xh[1]);
                    mma16816(yh[2 * np + 1], gah, xh[2], xh[3]);
                    mma16816(yh[2 * np],     gah, xl[0], xl[1]);
                    mma16816(yh[2 * np + 1], gah, xl[2], xl[3]);
                    mma16816(yh[2 * np],     gal, xh[0], xh[1]);
                    mma16816(yh[2 * np + 1], gal, xh[2], xh[3]);
                }
            }
        }
    }

    // epilogue: + x*D, write g_y for both heads
    int r0 = Lrow0 + l0row;
#pragma unroll
    for (int hh = 0; hh < 2; hh++) {
        int h = hh ? h1 : h0;
        float dh = Dv[h];
        float (*yh)[4] = hh ? yacc1 : yacc0;
#pragma unroll
        for (int j = 0; j < 8; j++) {
            int p = h * 64 + 8 * j + 2 * (lane & 3);
            float2 x0 = *(const float2*)&g_x[(size_t)r0 * INTER + p];
            float2 x1 = *(const float2*)&g_x[(size_t)(r0 + 8) * INTER + p];
            *(float2*)&g_y[(size_t)r0 * INTER + p] =
                make_float2(yh[j][0] + x0.x * dh, yh[j][1] + x0.y * dh);
            *(float2*)&g_y[(size_t)(r0 + 8) * INTER + p] =
                make_float2(yh[j][2] + x1.x * dh, yh[j][3] + x1.y * dh);
        }
    }
}

// ---------------- gated RMSNorm fused with bf16 hi/lo split ----------------
__global__ void rmsnorm_split_kernel(const float* __restrict__ nw) {
    int l = blockIdx.x;
    int tid = threadIdx.x;
    float v[16];
    float ss = 0.f;
#pragma unroll
    for (int i = 0; i < 16; i++) {
        int col = tid + i * 256;
        float y = g_y[(size_t)l * INTER + col];
        float z = g_zx[(size_t)l * OUT_IN + col];
        float yf = y * (z / (1.f + expf(-z)));
        v[i] = yf;
        ss = fmaf(yf, yf, ss);
    }
    __shared__ float red[256];
    red[tid] = ss;
    __syncthreads();
    for (int o = 128; o > 0; o >>= 1) {
        if (tid < o) red[tid] += red[tid + o];
        __syncthreads();
    }
    float scale = rsqrtf(red[0] / (float)INTER + 1e-5f);
#pragma unroll
    for (int i = 0; i < 16; i++) {
        int col = tid + i * 256;
        float yn = v[i] * scale * nw[col];
        __nv_bfloat16 h, lo;
        split2(yn, h, lo);
        gA2h[(size_t)l * INTER + col] = h;
        gA2l[(size_t)l * INTER + col] = lo;
    }
}

// ---------------- launch ----------------
extern "C" void kernel_launch(void* const* d_in, const int* in_sizes, int n_in,
                              void* d_out, int out_size) {
    const float* hs      = (const float*)d_in[0];
    const float* W_in    = (const float*)d_in[1];
    const float* conv_w  = (const float*)d_in[2];
    const float* conv_b  = (const float*)d_in[3];
    const float* dt_bias = (const float*)d_in[4];
    const float* A_log   = (const float*)d_in[5];
    const float* Dv      = (const float*)d_in[6];
    const float* norm_w  = (const float*)d_in[7];
    const float* W_out   = (const float*)d_in[8];
    float* out = (float*)d_out;

    void *p_zx;
    void *pA1h, *pA1l, *pB1h, *pB1l, *pA2h, *pA2l, *pB2h, *pB2l;
    cudaGetSymbolAddress(&p_zx, g_zx);
    cudaGetSymbolAddress(&pA1h, gA1h); cudaGetSymbolAddress(&pA1l, gA1l);
    cudaGetSymbolAddress(&pB1h, gB1h); cudaGetSymbolAddress(&pB1l, gB1l);
    cudaGetSymbolAddress(&pA2h, gA2h); cudaGetSymbolAddress(&pA2l, gA2l);
    cudaGetSymbolAddress(&pB2h, gB2h); cudaGetSymbolAddress(&pB2l, gB2l);

    const int GSMEM = NSTG * STAGE_B;   // 102400 -> 2 CTAs/SM
    cudaFuncSetAttribute(gemm_hmma, cudaFuncAttributeMaxDynamicSharedMemorySize, GSMEM);
    cudaFuncSetAttribute(y_hmma, cudaFuncAttributeMaxDynamicSharedMemorySize, YSMEM2);
    cudaFuncSetAttribute(states_hmma, cudaFuncAttributeMaxDynamicSharedMemorySize, 54272);

    // 1) split hs -> A1
    split_kernel<<<(L_ * HIDD / 4 + 255) / 256, 256>>>(hs, (__nv_bfloat16*)pA1h, (__nv_bfloat16*)pA1l, L_ * HIDD / 4);
    // 2) transpose+split W_in -> B1
    transpose_split_kernel<<<dim3(OUT_IN_PAD / 32, HIDD / 32), dim3(32, 8)>>>(
        W_in, (__nv_bfloat16*)pB1h, (__nv_bfloat16*)pB1l, HIDD, OUT_IN);
    // 3) transpose+split W_out -> B2
    transpose_split_kernel<<<dim3(HIDD / 32, INTER / 32), dim3(32, 8)>>>(
        W_out, (__nv_bfloat16*)pB2h, (__nv_bfloat16*)pB2l, INTER, HIDD);
    // 4) zxbcdt = hs @ W_in   <-- profiled launch
    gemm_hmma<<<dim3(OUT_IN_PAD / 128, L_ / 128), 256, GSMEM>>>(
        (const __nv_bfloat16*)pA1h, (const __nv_bfloat16*)pA1l,
        (const __nv_bfloat16*)pB1h, (const __nv_bfloat16*)pB1l,
        (float*)p_zx, OUT_IN, HIDD);
    // 5) dt + per-chunk cumsum
    dtcs_kernel<<<dim3(NC, Hh), 256>>>(dt_bias, A_log);
    // 6) fused conv + silu + xdt/BC splits
    conv_fused_kernel<<<dim3(CONV_DIM / 256, L_), 256>>>(conv_w, conv_b);
    // 7) per-chunk states (HMMA)
    states_hmma<<<dim3(NC, Hh), 128, 54272>>>();
    // 8) inter-chunk scan
    scan_kernel<<<(Hh * Pp * Nn) / 256, 256>>>();
    // 9) Y (HMMA, head-paired)
    y_hmma<<<dim3(4, NC, Hh / 2), 128, YSMEM2>>>(Dv);
    // 10) gated RMSNorm + split A2
    rmsnorm_split_kernel<<<L_, 256>>>(norm_w);
    // 11) out = yn @ W_out
    gemm_hmma<<<dim3(HIDD / 128, L_ / 128), 256, GSMEM>>>(
        (const __nv_bfloat16*)pA2h, (const __nv_bfloat16*)pA2l,
        (const __nv_bfloat16*)pB2h, (const __nv_bfloat16*)pB2l,
        out, HIDD, INTER);
}

// round 15
// speedup vs baseline: 1.0183x; 1.0183x over previous
#include <cuda_runtime.h>
#include <cuda_bf16.h>
#include <math.h>
#include <cstdint>

// ---------------- problem constants ----------------
#define L_       4096
#define HIDD     2048
#define Hh       64
#define Pp       64
#define Nn       128
#define CHh      256
#define NC       16
#define INTER    4096
#define CONV_DIM 4352            // INTER + 2N
#define OUT_IN   8512            // 2*(INTER+N) + H
#define OUT_IN_PAD 8576          // 67 * 128
#define XBC_OFF  INTER
#define DTRAW_OFF (2*INTER + 2*Nn)

// ---------------- device scratch (static; no runtime alloc) ----------------
__device__ float g_zx[L_ * OUT_IN];
__device__ float g_x[L_ * INTER];
__device__ float g_dt[NC * Hh * CHh];
__device__ float g_acs[NC * Hh * CHh];
__device__ float g_states[NC * Hh * Pp * Nn];
__device__ float g_y[L_ * INTER];

__device__ __nv_bfloat16 gA1h[L_ * HIDD];
__device__ __nv_bfloat16 gA1l[L_ * HIDD];
__device__ __nv_bfloat16 gB1h[OUT_IN_PAD * HIDD];
__device__ __nv_bfloat16 gB1l[OUT_IN_PAD * HIDD];
__device__ __nv_bfloat16 gA2h[L_ * INTER];
__device__ __nv_bfloat16 gA2l[L_ * INTER];
__device__ __nv_bfloat16 gB2h[HIDD * INTER];
__device__ __nv_bfloat16 gB2l[HIDD * INTER];

__device__ __nv_bfloat16 g_xdth[L_ * INTER];
__device__ __nv_bfloat16 g_xdtl[L_ * INTER];
__device__ __nv_bfloat16 g_bch[L_ * 256];
__device__ __nv_bfloat16 g_bcl[L_ * 256];
__device__ __nv_bfloat16 g_stinh[NC * Hh * Pp * Nn];
__device__ __nv_bfloat16 g_stinl[NC * Hh * Pp * Nn];

// ================= low-level helpers =================
__device__ __forceinline__ uint32_t smem_u32(const void* p) {
    uint32_t a;
    asm("{ .reg .u64 t; cvta.to.shared.u64 t, %1; cvt.u32.u64 %0, t; }" : "=r"(a) : "l"(p));
    return a;
}
#define CP16(sm, gm) \
    asm volatile("cp.async.cg.shared.global [%0], [%1], 16;" :: "r"(sm), "l"(gm) : "memory")
#define CP_COMMIT() asm volatile("cp.async.commit_group;" ::: "memory")
#define CP_WAIT(n)  asm volatile("cp.async.wait_group %0;" :: "n"(n) : "memory")

__device__ __forceinline__ void ldsm_x4(uint32_t& r0, uint32_t& r1, uint32_t& r2, uint32_t& r3,
                                        uint32_t addr) {
    asm volatile("ldmatrix.sync.aligned.m8n8.x4.shared.b16 {%0,%1,%2,%3}, [%4];"
                 : "=r"(r0), "=r"(r1), "=r"(r2), "=r"(r3) : "r"(addr));
}
__device__ __forceinline__ void ldsm_x4_t(uint32_t& r0, uint32_t& r1, uint32_t& r2, uint32_t& r3,
                                          uint32_t addr) {
    asm volatile("ldmatrix.sync.aligned.m8n8.x4.trans.shared.b16 {%0,%1,%2,%3}, [%4];"
                 : "=r"(r0), "=r"(r1), "=r"(r2), "=r"(r3) : "r"(addr));
}
__device__ __forceinline__ void mma16816(float* d, const uint32_t* a, uint32_t b0, uint32_t b1) {
    asm volatile("mma.sync.aligned.m16n8k16.row.col.f32.bf16.bf16.f32 "
                 "{%0,%1,%2,%3}, {%4,%5,%6,%7}, {%8,%9}, {%0,%1,%2,%3};"
                 : "+f"(d[0]), "+f"(d[1]), "+f"(d[2]), "+f"(d[3])
                 : "r"(a[0]), "r"(a[1]), "r"(a[2]), "r"(a[3]), "r"(b0), "r"(b1));
}
__device__ __forceinline__ uint32_t pk(__nv_bfloat16 a, __nv_bfloat16 b) {
    __nv_bfloat162 t; t.x = a; t.y = b;
    return *reinterpret_cast<uint32_t*>(&t);
}
__device__ __forceinline__ void split2(float x, __nv_bfloat16& h, __nv_bfloat16& l) {
    h = __float2bfloat16(x);
    l = __float2bfloat16(x - __bfloat162float(h));
}

// ================= split / transpose conversion kernels =================
__global__ void split_kernel(const float* __restrict__ in, __nv_bfloat16* __restrict__ hi,
                             __nv_bfloat16* __restrict__ lo, int n4) {
    int i = blockIdx.x * 256 + threadIdx.x;
    if (i >= n4) return;
    float4 v = ((const float4*)in)[i];
    __nv_bfloat16 h0, h1, h2, h3, l0, l1, l2, l3;
    split2(v.x, h0, l0); split2(v.y, h1, l1); split2(v.z, h2, l2); split2(v.w, h3, l3);
    ((uint2*)hi)[i] = make_uint2(pk(h0, h1), pk(h2, h3));
    ((uint2*)lo)[i] = make_uint2(pk(l0, l1), pk(l2, l3));
}

__global__ void transpose_split_kernel(const float* __restrict__ W,
                                       __nv_bfloat16* __restrict__ outH,
                                       __nv_bfloat16* __restrict__ outL,
                                       int K, int N) {
    __shared__ float tile[32][33];
    int n0 = blockIdx.x * 32, k0 = blockIdx.y * 32;
    int tx = threadIdx.x, ty = threadIdx.y;
#pragma unroll
    for (int i = 0; i < 4; i++) {
        int k = k0 + ty + i * 8;
        int n = n0 + tx;
        tile[ty + i * 8][tx] = (n < N) ? W[(size_t)k * N + n] : 0.f;
    }
    __syncthreads();
#pragma unroll
    for (int i = 0; i < 4; i++) {
        int nrow = n0 + ty + i * 8;
        int kcol = k0 + tx;
        float x = tile[tx][ty + i * 8];
        __nv_bfloat16 h, l;
        split2(x, h, l);
        outH[(size_t)nrow * K + kcol] = h;
        outL[(size_t)nrow * K + kcol] = l;
    }
}

// ================= HMMA split-bf16 GEMM: packed hi/lo rows, 5 stages (R13 order) =================
#define KT      16
#define PITCHB  80
#define PARR_B  (128 * PITCHB)
#define STAGE_B (2 * PARR_B)
#define NSTG    5

extern __shared__ __align__(128) char gsm_raw[];

__global__ void __launch_bounds__(256, 2)
gemm_hmma(const __nv_bfloat16* __restrict__ Ah, const __nv_bfloat16* __restrict__ Al,
          const __nv_bfloat16* __restrict__ Bh, const __nv_bfloat16* __restrict__ Bl,
          float* __restrict__ C, int Nreal, int K) {
    const int tid = threadIdx.x;
    const int lane = tid & 31, wid = tid >> 5;
    const int wm = wid & 1, wn = wid >> 1;
    const int row0 = blockIdx.y * 128, col0 = blockIdx.x * 128;
    const uint32_t sb = smem_u32(gsm_raw);

    const int lrow = tid >> 1;
    const int lelem = (tid & 1) * 8;
    const __nv_bfloat16* pAh = Ah + (size_t)(row0 + lrow) * K + lelem;
    const __nv_bfloat16* pAl = Al + (size_t)(row0 + lrow) * K + lelem;
    const __nv_bfloat16* pBh = Bh + (size_t)(col0 + lrow) * K + lelem;
    const __nv_bfloat16* pBl = Bl + (size_t)(col0 + lrow) * K + lelem;
    const uint32_t dstA = lrow * PITCHB + (tid & 1) * 16;

    float acc[4][4][4];
#pragma unroll
    for (int m = 0; m < 4; m++)
#pragma unroll
        for (int n = 0; n < 4; n++)
#pragma unroll
            for (int v = 0; v < 4; v++) acc[m][n][v] = 0.f;

    const int T = K / KT;

#define GFILL_NC(sidx, ko) do { \
        uint32_t _s = sb + (sidx) * STAGE_B; \
        CP16(_s + dstA,               pAh + (ko)); \
        CP16(_s + dstA + 32,          pAl + (ko)); \
        CP16(_s + PARR_B + dstA,      pBh + (ko)); \
        CP16(_s + PARR_B + dstA + 32, pBl + (ko)); \
    } while (0)

#pragma unroll
    for (int t = 0; t < 4; t++) {
        GFILL_NC(t, t * KT);
        CP_COMMIT();
    }

    const uint32_t a_frag_base = (wm * 64 + (lane & 15)) * PITCHB + (lane >> 4) * 16;
    const uint32_t b_frag_base = (wn * 32 + (lane & 7) + (lane >> 4) * 8) * PITCHB
                                 + ((lane >> 3) & 1) * 16;

    int sread = 0, sfill = 4;
    for (int t = 0; t < T; t++) {
        CP_WAIT(2);
        __syncthreads();
        if (t + 4 < T) GFILL_NC(sfill, (t + 4) * KT);
        CP_COMMIT();

        const uint32_t st = sb + sread * STAGE_B;
        uint32_t bh[2][4], bl[2][4];
#pragma unroll
        for (int np = 0; np < 2; np++) {
            uint32_t bo = st + PARR_B + b_frag_base + np * (16 * PITCHB);
            ldsm_x4(bh[np][0], bh[np][1], bh[np][2], bh[np][3], bo);
            ldsm_x4(bl[np][0], bl[np][1], bl[np][2], bl[np][3], bo + 32);
        }
#pragma unroll
        for (int mt = 0; mt < 4; mt++) {
            uint32_t ah[4], al[4];
            uint32_t ao = st + a_frag_base + mt * (16 * PITCHB);
            ldsm_x4(ah[0], ah[1], ah[2], ah[3], ao);
            ldsm_x4(al[0], al[1], al[2], al[3], ao + 32);
#pragma unroll
            for (int nt = 0; nt < 4; nt++) {
                int np = nt >> 1, hv = (nt & 1) * 2;
                mma16816(acc[mt][nt], ah, bh[np][hv], bh[np][hv + 1]);
                mma16816(acc[mt][nt], ah, bl[np][hv], bl[np][hv + 1]);
                mma16816(acc[mt][nt], al, bh[np][hv], bh[np][hv + 1]);
            }
        }
        sread = (sread + 1 == NSTG) ? 0 : sread + 1;
        sfill = (sfill + 1 == NSTG) ? 0 : sfill + 1;
    }

#pragma unroll
    for (int mt = 0; mt < 4; mt++) {
        int r = row0 + wm * 64 + mt * 16 + (lane >> 2);
#pragma unroll
        for (int nt = 0; nt < 4; nt++) {
            int c = col0 + wn * 32 + nt * 8 + (lane & 3) * 2;
            if (c < Nreal) {
                *(float2*)&C[(size_t)r * Nreal + c]       = make_float2(acc[mt][nt][0], acc[mt][nt][1]);
                *(float2*)&C[(size_t)(r + 8) * Nreal + c] = make_float2(acc[mt][nt][2], acc[mt][nt][3]);
            }
        }
    }
#undef GFILL_NC
}

// ---------------- dt (softplus+clip) and per-chunk cumsum of dt*A ----------------
__global__ void dtcs_kernel(const float* __restrict__ dt_bias, const float* __restrict__ A_log) {
    int c = blockIdx.x, h = blockIdx.y;
    int t = threadIdx.x;
    int Lg = c * CHh + t;
    float raw = g_zx[(size_t)Lg * OUT_IN + DTRAW_OFF + h] + dt_bias[h];
    float sp = (raw > 20.f) ? raw : log1pf(expf(raw));
    float dt = fminf(fmaxf(sp, 0.f), 100.f);
    float A = -expf(A_log[h]);
    __shared__ float s[256];
    s[t] = dt * A;
    __syncthreads();
    for (int off = 1; off < 256; off <<= 1) {
        float v = (t >= off) ? s[t - off] : 0.f;
        __syncthreads();
        s[t] += v;
        __syncthreads();
    }
    int base = (c * Hh + h) * CHh;
    g_dt[base + t] = dt;
    g_acs[base + t] = s[t];
}

// ---------------- fused: causal conv + silu + xdt/BC bf16 split ----------------
__global__ void conv_fused_kernel(const float* __restrict__ cw, const float* __restrict__ cb) {
    int c = blockIdx.x * 256 + threadIdx.x;
    int l = blockIdx.y;
    float acc = cb[c];
#pragma unroll
    for (int k = 0; k < 4; k++) {
        int ll = l + k - 3;
        if (ll >= 0) acc = fmaf(g_zx[(size_t)ll * OUT_IN + XBC_OFF + c], cw[k * CONV_DIM + c], acc);
    }
    float s = acc / (1.f + expf(-acc));
    if (c < INTER) {
        int h = c >> 6;
        float dtv = g_dt[((l >> 8) * Hh + h) * CHh + (l & 255)];
        g_x[(size_t)l * INTER + c] = s;
        __nv_bfloat16 hh, ll2;
        split2(s * dtv, hh, ll2);
        g_xdth[(size_t)l * INTER + c] = hh;
        g_xdtl[(size_t)l * INTER + c] = ll2;
    } else {
        int cc = c - INTER;
        __nv_bfloat16 hh, ll2;
        split2(s, hh, ll2);
        g_bch[(size_t)l * 256 + cc] = hh;
        g_bcl[(size_t)l * 256 + cc] = ll2;
    }
}

// ---------------- HMMA states (cp.async B staging overlapped with X' compute) ----------------
extern __shared__ __align__(128) char ssm2[];
__global__ void __launch_bounds__(128, 2)
states_hmma() {
    const uint32_t sb = smem_u32(ssm2);
    const int tid = threadIdx.x, lane = tid & 31, w = tid >> 5;
    const int c = blockIdx.x, h = blockIdx.y;
    const int base = (c * Hh + h) * CHh;
    const float aend = g_acs[base + 255];
    float* wb = (float*)(ssm2 + 53248);
    for (int t = tid; t < 256; t += 128) wb[t] = expf(aend - g_acs[base + t]);

    float sacc[16][4];
#pragma unroll
    for (int j = 0; j < 16; j++)
#pragma unroll
        for (int v = 0; v < 4; v++) sacc[j][v] = 0.f;

    const uint32_t axb = sb + ((lane & 7) + (lane >> 4) * 8) * 144 + 32 * w + ((lane >> 3) & 1) * 16;
    const uint32_t bxb = sb + 18432 + ((lane & 7) + ((lane >> 3) & 1) * 8) * 272 + (lane >> 4) * 16;

    for (int kt = 0; kt < 4; kt++) {
        __syncthreads();
        int l0 = kt * 64;
        for (int e = tid; e < 1024; e += 128) {
            int row = e >> 4, s = e & 15;
            int lg = c * CHh + l0 + row;
            CP16(sb + 18432 + row * 272 + s * 16, &g_bch[(size_t)lg * 256 + s * 8]);
            CP16(sb + 35840 + row * 272 + s * 16, &g_bcl[(size_t)lg * 256 + s * 8]);
        }
        CP_COMMIT();
        for (int e = tid; e < 2048; e += 128) {
            int row = e >> 5, seg = e & 31;
            int lg = c * CHh + l0 + row;
            __nv_bfloat162 xh2 = *(const __nv_bfloat162*)&g_xdth[(size_t)lg * INTER + h * 64 + seg * 2];
            __nv_bfloat162 xl2 = *(const __nv_bfloat162*)&g_xdtl[(size_t)lg * INTER + h * 64 + seg * 2];
            float wv = wb[l0 + row];
            float v0 = (__bfloat162float(xh2.x) + __bfloat162float(xl2.x)) * wv;
            float v1 = (__bfloat162float(xh2.y) + __bfloat162float(xl2.y)) * wv;
            __nv_bfloat16 a0, a1, b0, b1;
            split2(v0, a0, b0); split2(v1, a1, b1);
            *(uint32_t*)(ssm2 + row * 144 + seg * 4) = pk(a0, a1);
            *(uint32_t*)(ssm2 + 9216 + row * 144 + seg * 4) = pk(b0, b1);
        }
        CP_WAIT(0);
        __syncthreads();

#pragma unroll
        for (int t = 0; t < 4; t++) {
            uint32_t ah[4], al[4];
            ldsm_x4_t(ah[0], ah[1], ah[2], ah[3], axb + t * 2304);
            ldsm_x4_t(al[0], al[1], al[2], al[3], axb + 9216 + t * 2304);
#pragma unroll
            for (int np = 0; np < 8; np++) {
                uint32_t bh[4], bl[4];
                ldsm_x4_t(bh[0], bh[1], bh[2], bh[3], bxb + t * 4352 + np * 32);
                ldsm_x4_t(bl[0], bl[1], bl[2], bl[3], bxb + 17408 + t * 4352 + np * 32);
                mma16816(sacc[2 * np],     ah, bh[0], bh[1]);
                mma16816(sacc[2 * np + 1], ah, bh[2], bh[3]);
                mma16816(sacc[2 * np],     ah, bl[0], bl[1]);
                mma16816(sacc[2 * np + 1], ah, bl[2], bl[3]);
                mma16816(sacc[2 * np],     al, bh[0], bh[1]);
                mma16816(sacc[2 * np + 1], al, bh[2], bh[3]);
            }
        }
    }

    float* out = g_states + (size_t)(c * Hh + h) * 8192;
    int p0 = 16 * w + (lane >> 2);
#pragma unroll
    for (int j = 0; j < 16; j++) {
        int n = 8 * j + 2 * (lane & 3);
        *(float2*)&out[p0 * 128 + n]       = make_float2(sacc[j][0], sacc[j][1]);
        *(float2*)&out[(p0 + 8) * 128 + n] = make_float2(sacc[j][2], sacc[j][3]);
    }
}

// ---------------- inter-chunk state scan (emits split stin) ----------------
__global__ void scan_kernel() {
    int idx = blockIdx.x * 256 + threadIdx.x;
    int h = idx >> 13;
    int rem = idx & 8191;
    float st = 0.f;
    for (int c = 0; c < NC; c++) {
        size_t o = (size_t)(c * Hh + h) * 8192 + rem;
        __nv_bfloat16 hi, lo;
        split2(st, hi, lo);
        g_stinh[o] = hi;
        g_stinl[o] = lo;
        float cend = g_acs[(c * Hh + h) * CHh + 255];
        st = st * expf(cend) + g_states[o];
    }
}

// ---------------- HMMA fused Y kernel: head-paired + overlapped prologue ----------------
#define OFF_CL   17408
#define OFF_UH   34816
#define OFF_UL   52224
#define OFF_X0H  69632
#define OFF_X0L  78848
#define OFF_X1H  88064
#define OFF_X1L  97280
#define OFF_S1H  69632            // Sin_h1 hi (aliases X region during prologue)
#define OFF_S1L  87040            // Sin_h1 lo
#define OFF_AL0  106496
#define OFF_AL1  106752
#define OFF_AS0  107008
#define OFF_AS1  107264
#define YSMEM2   107520
extern __shared__ __align__(128) char ysm2[];
__global__ void __launch_bounds__(128, 2)
y_hmma(const float* __restrict__ Dv) {
    const uint32_t sb = smem_u32(ysm2);
    const int tid = threadIdx.x, lane = tid & 31, w = tid >> 5;
    const int lt = blockIdx.x, c = blockIdx.y, hp = blockIdx.z;
    const int h0 = 2 * hp, h1 = 2 * hp + 1;
    const int base0 = (c * Hh + h0) * CHh;
    const int base1 = (c * Hh + h1) * CHh;
    const int Lrow0 = c * CHh + lt * 64;
    float* acsl0 = (float*)(ysm2 + OFF_AL0);
    float* acsl1 = (float*)(ysm2 + OFF_AL1);
    float* acss0 = (float*)(ysm2 + OFF_AS0);
    float* acss1 = (float*)(ysm2 + OFF_AS1);

    const uint32_t a_base = sb + (16 * w + (lane & 15)) * 272 + (lane >> 4) * 16;
    const uint32_t b_base = sb + OFF_UH + ((lane & 7) + (lane >> 4) * 8) * 272 + ((lane >> 3) & 1) * 16;
    const uint32_t s1_base = sb + OFF_S1H + ((lane & 7) + (lane >> 4) * 8) * 272 + ((lane >> 3) & 1) * 16;
    const uint32_t x0_base = sb + OFF_X0H + ((lane & 7) + ((lane >> 3) & 1) * 8) * 144 + (lane >> 4) * 16;
    const uint32_t x1_base = sb + OFF_X1H + ((lane & 7) + ((lane >> 3) & 1) * 8) * 144 + (lane >> 4) * 16;

    float yacc0[8][4], yacc1[8][4];
#pragma unroll
    for (int j = 0; j < 8; j++)
#pragma unroll
        for (int v = 0; v < 4; v++) { yacc0[j][v] = 0.f; yacc1[j][v] = 0.f; }

    // stage 1: C tile (shared) + Sin_h0 (UH) + Sin_h1 (X region alias) in ONE group
    {
        const size_t sinb0 = (size_t)(c * Hh + h0) * 8192;
        const size_t sinb1 = (size_t)(c * Hh + h1) * 8192;
        for (int e = tid; e < 1024; e += 128) {
            int row = e >> 4, s = e & 15;
            CP16(sb + row * 272 + s * 16,           &g_bch[(size_t)(Lrow0 + row) * 256 + 128 + s * 8]);
            CP16(sb + OFF_CL + row * 272 + s * 16,  &g_bcl[(size_t)(Lrow0 + row) * 256 + 128 + s * 8]);
            CP16(sb + OFF_UH + row * 272 + s * 16,  &g_stinh[sinb0 + row * 128 + s * 8]);
            CP16(sb + OFF_UL + row * 272 + s * 16,  &g_stinl[sinb0 + row * 128 + s * 8]);
            CP16(sb + OFF_S1H + row * 272 + s * 16, &g_stinh[sinb1 + row * 128 + s * 8]);
            CP16(sb + OFF_S1L + row * 272 + s * 16, &g_stinl[sinb1 + row * 128 + s * 8]);
        }
        if (tid < 64) { acsl0[tid] = g_acs[base0 + lt * 64 + tid]; acsl1[tid] = g_acs[base1 + lt * 64 + tid]; }
        CP_COMMIT();
        CP_WAIT(0);
    }
    __syncthreads();

    // Y_off h0 = C . Sin0^T, scaled
#pragma unroll
    for (int kk = 0; kk < 8; kk++) {
        uint32_t ah[4], al[4];
        ldsm_x4(ah[0], ah[1], ah[2], ah[3], a_base + kk * 32);
        ldsm_x4(al[0], al[1], al[2], al[3], a_base + OFF_CL + kk * 32);
#pragma unroll
        for (int np = 0; np < 4; np++) {
            uint32_t bh[4], bl[4];
            ldsm_x4(bh[0], bh[1], bh[2], bh[3], b_base + np * 4352 + kk * 32);
            ldsm_x4(bl[0], bl[1], bl[2], bl[3], b_base + 17408 + np * 4352 + kk * 32);
            mma16816(yacc0[2 * np],     ah, bh[0], bh[1]);
            mma16816(yacc0[2 * np + 1], ah, bh[2], bh[3]);
            mma16816(yacc0[2 * np],     ah, bl[0], bl[1]);
            mma16816(yacc0[2 * np + 1], ah, bl[2], bl[3]);
            mma16816(yacc0[2 * np],     al, bh[0], bh[1]);
            mma16816(yacc0[2 * np + 1], al, bh[2], bh[3]);
        }
    }
    {
        float e0 = expf(acsl0[16 * w + (lane >> 2)]);
        float e1 = expf(acsl0[16 * w + (lane >> 2) + 8]);
#pragma unroll
        for (int j = 0; j < 8; j++) {
            yacc0[j][0] *= e0; yacc0[j][1] *= e0;
            yacc0[j][2] *= e1; yacc0[j][3] *= e1;
        }
    }

    // UH free -> issue B(st=0) now; it streams in while we compute Y_off h1
    __syncthreads();
    {
        const int Srow0 = c * CHh;   // st = 0
        for (int e = tid; e < 1024; e += 128) {
            int row = e >> 4, s = e & 15;
            CP16(sb + OFF_UH + row * 272 + s * 16, &g_bch[(size_t)(Srow0 + row) * 256 + s * 8]);
            CP16(sb + OFF_UL + row * 272 + s * 16, &g_bcl[(size_t)(Srow0 + row) * 256 + s * 8]);
        }
        CP_COMMIT();
    }

    // Y_off h1 = C . Sin1^T (from aliased X region), scaled
#pragma unroll
    for (int kk = 0; kk < 8; kk++) {
        uint32_t ah[4], al[4];
        ldsm_x4(ah[0], ah[1], ah[2], ah[3], a_base + kk * 32);
        ldsm_x4(al[0], al[1], al[2], al[3], a_base + OFF_CL + kk * 32);
#pragma unroll
        for (int np = 0; np < 4; np++) {
            uint32_t bh[4], bl[4];
            ldsm_x4(bh[0], bh[1], bh[2], bh[3], s1_base + np * 4352 + kk * 32);
            ldsm_x4(bl[0], bl[1], bl[2], bl[3], s1_base + (OFF_S1L - OFF_S1H) + np * 4352 + kk * 32);
            mma16816(yacc1[2 * np],     ah, bh[0], bh[1]);
            mma16816(yacc1[2 * np + 1], ah, bh[2], bh[3]);
            mma16816(yacc1[2 * np],     ah, bl[0], bl[1]);
            mma16816(yacc1[2 * np + 1], ah, bl[2], bl[3]);
            mma16816(yacc1[2 * np],     al, bh[0], bh[1]);
            mma16816(yacc1[2 * np + 1], al, bh[2], bh[3]);
        }
    }
    {
        float e0 = expf(acsl1[16 * w + (lane >> 2)]);
        float e1 = expf(acsl1[16 * w + (lane >> 2) + 8]);
#pragma unroll
        for (int j = 0; j < 8; j++) {
            yacc1[j][0] *= e0; yacc1[j][1] *= e0;
            yacc1[j][2] *= e1; yacc1[j][3] *= e1;
        }
    }

    const int l0row = 16 * w + (lane >> 2);

    for (int st = 0; st <= lt; st++) {
        const int Srow0 = c * CHh + st * 64;
        __syncthreads();
        if (st > 0) {   // B(0) already in flight from the prologue
            for (int e = tid; e < 1024; e += 128) {
                int row = e >> 4, s = e & 15;
                CP16(sb + OFF_UH + row * 272 + s * 16, &g_bch[(size_t)(Srow0 + row) * 256 + s * 8]);
                CP16(sb + OFF_UL + row * 272 + s * 16, &g_bcl[(size_t)(Srow0 + row) * 256 + s * 8]);
            }
        }
        for (int e = tid; e < 512; e += 128) {
            int row = e >> 3, s = e & 7;
            CP16(sb + OFF_X0H + row * 144 + s * 16, &g_xdth[(size_t)(Srow0 + row) * INTER + h0 * 64 + s * 8]);
            CP16(sb + OFF_X0L + row * 144 + s * 16, &g_xdtl[(size_t)(Srow0 + row) * INTER + h0 * 64 + s * 8]);
            CP16(sb + OFF_X1H + row * 144 + s * 16, &g_xdth[(size_t)(Srow0 + row) * INTER + h1 * 64 + s * 8]);
            CP16(sb + OFF_X1L + row * 144 + s * 16, &g_xdtl[(size_t)(Srow0 + row) * INTER + h1 * 64 + s * 8]);
        }
        if (tid < 64) { acss0[tid] = g_acs[base0 + st * 64 + tid]; acss1[tid] = g_acs[base1 + st * 64 + tid]; }
        CP_COMMIT();
        CP_WAIT(0);
        __syncthreads();

        // raw G = C . B^T (shared across both heads)
        float gacc[8][4];
#pragma unroll
        for (int j = 0; j < 8; j++)
#pragma unroll
            for (int v = 0; v < 4; v++) gacc[j][v] = 0.f;
#pragma unroll
        for (int kk = 0; kk < 8; kk++) {
            uint32_t ah[4], al[4];
            ldsm_x4(ah[0], ah[1], ah[2], ah[3], a_base + kk * 32);
            ldsm_x4(al[0], al[1], al[2], al[3], a_base + OFF_CL + kk * 32);
#pragma unroll
            for (int np = 0; np < 4; np++) {
                uint32_t bh[4], bl[4];
                ldsm_x4(bh[0], bh[1], bh[2], bh[3], b_base + np * 4352 + kk * 32);
                ldsm_x4(bl[0], bl[1], bl[2], bl[3], b_base + 17408 + np * 4352 + kk * 32);
                mma16816(gacc[2 * np],     ah, bh[0], bh[1]);
                mma16816(gacc[2 * np + 1], ah, bh[2], bh[3]);
                mma16816(gacc[2 * np],     ah, bl[0], bl[1]);
                mma16816(gacc[2 * np + 1], ah, bl[2], bl[3]);
                mma16816(gacc[2 * np],     al, bh[0], bh[1]);
                mma16816(gacc[2 * np + 1], al, bh[2], bh[3]);
            }
        }

        const bool diag = (st == lt);
#pragma unroll
        for (int hh = 0; hh < 2; hh++) {
            const float* acslh = hh ? acsl1 : acsl0;
            const float* acssh = hh ? acss1 : acss0;
            const uint32_t xb = hh ? x1_base : x0_base;
            float (*yh)[4] = hh ? yacc1 : yacc0;
            float rA = acslh[l0row];
            float rB = acslh[l0row + 8];
#pragma unroll
            for (int t = 0; t < 4; t++) {
                uint32_t gah[4], gal[4];
#pragma unroll
                for (int half = 0; half < 2; half++) {
                    int j = 2 * t + half;
                    int s0 = 8 * j + 2 * (lane & 3);
                    float c0 = acssh[s0], c1 = acssh[s0 + 1];
                    float e00 = expf(rA - c0), e01 = expf(rA - c1);
                    float e10 = expf(rB - c0), e11 = expf(rB - c1);
                    if (diag) {
                        if (s0 > l0row)         e00 = 0.f;
                        if (s0 + 1 > l0row)     e01 = 0.f;
                        if (s0 > l0row + 8)     e10 = 0.f;
                        if (s0 + 1 > l0row + 8) e11 = 0.f;
                    }
                    float v0 = gacc[j][0] * e00, v1 = gacc[j][1] * e01;
                    float v2 = gacc[j][2] * e10, v3 = gacc[j][3] * e11;
                    __nv_bfloat16 p0, p1, p2, p3, q0, q1, q2, q3;
                    split2(v0, p0, q0); split2(v1, p1, q1);
                    split2(v2, p2, q2); split2(v3, p3, q3);
                    gah[2 * half]     = pk(p0, p1);
                    gah[2 * half + 1] = pk(p2, p3);
                    gal[2 * half]     = pk(q0, q1);
                    gal[2 * half + 1] = pk(q2, q3);
                }
#pragma unroll
                for (int np = 0; np < 4; np++) {
                    uint32_t xh[4], xl[4];
                    ldsm_x4_t(xh[0], xh[1], xh[2], xh[3], xb + t * 2304 + np * 32);
                    ldsm_x4_t(xl[0], xl[1], xl[2], xl[3], xb + 9216 + t * 2304 + np * 32);
                    mma16816(yh[2 * np],     gah, xh[0], xh[1]);
                    mma16816(yh[2 * np + 1], gah, xh[2], xh[3]);
                    mma16816(yh[2 * np],     gah, xl[0], xl[1]);
                    mma16816(yh[2 * np + 1], gah, xl[2], xl[3]);
                    mma16816(yh[2 * np],     gal, xh[0], xh[1]);
                    mma16816(yh[2 * np + 1], gal, xh[2], xh[3]);
                }
            }
        }
    }

    // epilogue: + x*D, write g_y for both heads
    int r0 = Lrow0 + l0row;
#pragma unroll
    for (int hh = 0; hh < 2; hh++) {
        int h = hh ? h1 : h0;
        float dh = Dv[h];
        float (*yh)[4] = hh ? yacc1 : yacc0;
#pragma unroll
        for (int j = 0; j < 8; j++) {
            int p = h * 64 + 8 * j + 2 * (lane & 3);
            float2 x0 = *(const float2*)&g_x[(size_t)r0 * INTER + p];
            float2 x1 = *(const float2*)&g_x[(size_t)(r0 + 8) * INTER + p];
            *(float2*)&g_y[(size_t)r0 * INTER + p] =
                make_float2(yh[j][0] + x0.x * dh, yh[j][1] + x0.y * dh);
            *(float2*)&g_y[(size_t)(r0 + 8) * INTER + p] =
                make_float2(yh[j][2] + x1.x * dh, yh[j][3] + x1.y * dh);
        }
    }
}

// ---------------- gated RMSNorm fused with bf16 hi/lo split ----------------
__global__ void rmsnorm_split_kernel(const float* __restrict__ nw) {
    int l = blockIdx.x;
    int tid = threadIdx.x;
    float v[16];
    float ss = 0.f;
#pragma unroll
    for (int i = 0; i < 16; i++) {
        int col = tid + i * 256;
        float y = g_y[(size_t)l * INTER + col];
        float z = g_zx[(size_t)l * OUT_IN + col];
        float yf = y * (z / (1.f + expf(-z)));
        v[i] = yf;
        ss = fmaf(yf, yf, ss);
    }
    __shared__ float red[256];
    red[tid] = ss;
    __syncthreads();
    for (int o = 128; o > 0; o >>= 1) {
        if (tid < o) red[tid] += red[tid + o];
        __syncthreads();
    }
    float scale = rsqrtf(red[0] / (float)INTER + 1e-5f);
#pragma unroll
    for (int i = 0; i < 16; i++) {
        int col = tid + i * 256;
        float yn = v[i] * scale * nw[col];
        __nv_bfloat16 h, lo;
        split2(yn, h, lo);
        gA2h[(size_t)l * INTER + col] = h;
        gA2l[(size_t)l * INTER + col] = lo;
    }
}

// ---------------- launch ----------------
extern "C" void kernel_launch(void* const* d_in, const int* in_sizes, int n_in,
                              void* d_out, int out_size) {
    const float* hs      = (const float*)d_in[0];
    const float* W_in    = (const float*)d_in[1];
    const float* conv_w  = (const float*)d_in[2];
    const float* conv_b  = (const float*)d_in[3];
    const float* dt_bias = (const float*)d_in[4];
    const float* A_log   = (const float*)d_in[5];
    const float* Dv      = (const float*)d_in[6];
    const float* norm_w  = (const float*)d_in[7];
    const float* W_out   = (const float*)d_in[8];
    float* out = (float*)d_out;

    void *p_zx;
    void *pA1h, *pA1l, *pB1h, *pB1l, *pA2h, *pA2l, *pB2h, *pB2l;
    cudaGetSymbolAddress(&p_zx, g_zx);
    cudaGetSymbolAddress(&pA1h, gA1h); cudaGetSymbolAddress(&pA1l, gA1l);
    cudaGetSymbolAddress(&pB1h, gB1h); cudaGetSymbolAddress(&pB1l, gB1l);
    cudaGetSymbolAddress(&pA2h, gA2h); cudaGetSymbolAddress(&pA2l, gA2l);
    cudaGetSymbolAddress(&pB2h, gB2h); cudaGetSymbolAddress(&pB2l, gB2l);

    const int GSMEM = NSTG * STAGE_B;   // 102400 -> 2 CTAs/SM
    cudaFuncSetAttribute(gemm_hmma, cudaFuncAttributeMaxDynamicSharedMemorySize, GSMEM);
    cudaFuncSetAttribute(y_hmma, cudaFuncAttributeMaxDynamicSharedMemorySize, YSMEM2);
    cudaFuncSetAttribute(states_hmma, cudaFuncAttributeMaxDynamicSharedMemorySize, 54272);

    // 1) split hs -> A1
    split_kernel<<<(L_ * HIDD / 4 + 255) / 256, 256>>>(hs, (__nv_bfloat16*)pA1h, (__nv_bfloat16*)pA1l, L_ * HIDD / 4);
    // 2) transpose+split W_in -> B1
    transpose_split_kernel<<<dim3(OUT_IN_PAD / 32, HIDD / 32), dim3(32, 8)>>>(
        W_in, (__nv_bfloat16*)pB1h, (__nv_bfloat16*)pB1l, HIDD, OUT_IN);
    // 3) transpose+split W_out -> B2
    transpose_split_kernel<<<dim3(HIDD / 32, INTER / 32), dim3(32, 8)>>>(
        W_out, (__nv_bfloat16*)pB2h, (__nv_bfloat16*)pB2l, INTER, HIDD);
    // 4) zxbcdt = hs @ W_in   <-- profiled launch
    gemm_hmma<<<dim3(OUT_IN_PAD / 128, L_ / 128), 256, GSMEM>>>(
        (const __nv_bfloat16*)pA1h, (const __nv_bfloat16*)pA1l,
        (const __nv_bfloat16*)pB1h, (const __nv_bfloat16*)pB1l,
        (float*)p_zx, OUT_IN, HIDD);
    // 5) dt + per-chunk cumsum
    dtcs_kernel<<<dim3(NC, Hh), 256>>>(dt_bias, A_log);
    // 6) fused conv + silu + xdt/BC splits
    conv_fused_kernel<<<dim3(CONV_DIM / 256, L_), 256>>>(conv_w, conv_b);
    // 7) per-chunk states (HMMA)
    states_hmma<<<dim3(NC, Hh), 128, 54272>>>();
    // 8) inter-chunk scan
    scan_kernel<<<(Hh * Pp * Nn) / 256, 256>>>();
    // 9) Y (HMMA, head-paired, overlapped prologue)
    y_hmma<<<dim3(4, NC, Hh / 2), 128, YSMEM2>>>(Dv);
    // 10) gated RMSNorm + split A2
    rmsnorm_split_kernel<<<L_, 256>>>(norm_w);
    // 11) out = yn @ W_out
    gemm_hmma<<<dim3(HIDD / 128, L_ / 128), 256, GSMEM>>>(
        (const __nv_bfloat16*)pA2h, (const __nv_bfloat16*)pA2l,
        (const __nv_bfloat16*)pB2h, (const __nv_bfloat16*)pB2l,
        out, HIDD, INTER);
}

// round 16
// speedup vs baseline: 1.0389x; 1.0202x over previous
#include <cuda_runtime.h>
#include <cuda_bf16.h>
#include <math.h>
#include <cstdint>

// ---------------- problem constants ----------------
#define L_       4096
#define HIDD     2048
#define Hh       64
#define Pp       64
#define Nn       128
#define CHh      256
#define NC       16
#define INTER    4096
#define CONV_DIM 4352            // INTER + 2N
#define OUT_IN   8512            // 2*(INTER+N) + H
#define OUT_IN_PAD 8576          // 67 * 128
#define XBC_OFF  INTER
#define DTRAW_OFF (2*INTER + 2*Nn)

// ---------------- device scratch (static; no runtime alloc) ----------------
__device__ float g_zx[L_ * OUT_IN];
__device__ float g_x[L_ * INTER];
__device__ float g_dt[NC * Hh * CHh];
__device__ float g_acs[NC * Hh * CHh];
__device__ float g_states[NC * Hh * Pp * Nn];
__device__ float g_y[L_ * INTER];

__device__ __nv_bfloat16 gA1h[L_ * HIDD];
__device__ __nv_bfloat16 gA1l[L_ * HIDD];
__device__ __nv_bfloat16 gB1h[OUT_IN_PAD * HIDD];
__device__ __nv_bfloat16 gB1l[OUT_IN_PAD * HIDD];
__device__ __nv_bfloat16 gA2h[L_ * INTER];
__device__ __nv_bfloat16 gA2l[L_ * INTER];
__device__ __nv_bfloat16 gB2h[HIDD * INTER];
__device__ __nv_bfloat16 gB2l[HIDD * INTER];

__device__ __nv_bfloat16 g_xdth[L_ * INTER];
__device__ __nv_bfloat16 g_xdtl[L_ * INTER];
__device__ __nv_bfloat16 g_bch[L_ * 256];
__device__ __nv_bfloat16 g_bcl[L_ * 256];
__device__ __nv_bfloat16 g_stinh[NC * Hh * Pp * Nn];
__device__ __nv_bfloat16 g_stinl[NC * Hh * Pp * Nn];

// ================= low-level helpers =================
__device__ __forceinline__ uint32_t smem_u32(const void* p) {
    uint32_t a;
    asm("{ .reg .u64 t; cvta.to.shared.u64 t, %1; cvt.u32.u64 %0, t; }" : "=r"(a) : "l"(p));
    return a;
}
#define CP16(sm, gm) \
    asm volatile("cp.async.cg.shared.global [%0], [%1], 16;" :: "r"(sm), "l"(gm) : "memory")
#define CP_COMMIT() asm volatile("cp.async.commit_group;" ::: "memory")
#define CP_WAIT(n)  asm volatile("cp.async.wait_group %0;" :: "n"(n) : "memory")

__device__ __forceinline__ void ldsm_x4(uint32_t& r0, uint32_t& r1, uint32_t& r2, uint32_t& r3,
                                        uint32_t addr) {
    asm volatile("ldmatrix.sync.aligned.m8n8.x4.shared.b16 {%0,%1,%2,%3}, [%4];"
                 : "=r"(r0), "=r"(r1), "=r"(r2), "=r"(r3) : "r"(addr));
}
__device__ __forceinline__ void ldsm_x4_t(uint32_t& r0, uint32_t& r1, uint32_t& r2, uint32_t& r3,
                                          uint32_t addr) {
    asm volatile("ldmatrix.sync.aligned.m8n8.x4.trans.shared.b16 {%0,%1,%2,%3}, [%4];"
                 : "=r"(r0), "=r"(r1), "=r"(r2), "=r"(r3) : "r"(addr));
}
__device__ __forceinline__ void mma16816(float* d, const uint32_t* a, uint32_t b0, uint32_t b1) {
    asm volatile("mma.sync.aligned.m16n8k16.row.col.f32.bf16.bf16.f32 "
                 "{%0,%1,%2,%3}, {%4,%5,%6,%7}, {%8,%9}, {%0,%1,%2,%3};"
                 : "+f"(d[0]), "+f"(d[1]), "+f"(d[2]), "+f"(d[3])
                 : "r"(a[0]), "r"(a[1]), "r"(a[2]), "r"(a[3]), "r"(b0), "r"(b1));
}
__device__ __forceinline__ uint32_t pk(__nv_bfloat16 a, __nv_bfloat16 b) {
    __nv_bfloat162 t; t.x = a; t.y = b;
    return *reinterpret_cast<uint32_t*>(&t);
}
__device__ __forceinline__ void split2(float x, __nv_bfloat16& h, __nv_bfloat16& l) {
    h = __float2bfloat16(x);
    l = __float2bfloat16(x - __bfloat162float(h));
}

// ================= split / transpose conversion kernels =================
__global__ void split_kernel(const float* __restrict__ in, __nv_bfloat16* __restrict__ hi,
                             __nv_bfloat16* __restrict__ lo, int n4) {
    int i = blockIdx.x * 256 + threadIdx.x;
    if (i >= n4) return;
    float4 v = ((const float4*)in)[i];
    __nv_bfloat16 h0, h1, h2, h3, l0, l1, l2, l3;
    split2(v.x, h0, l0); split2(v.y, h1, l1); split2(v.z, h2, l2); split2(v.w, h3, l3);
    ((uint2*)hi)[i] = make_uint2(pk(h0, h1), pk(h2, h3));
    ((uint2*)lo)[i] = make_uint2(pk(l0, l1), pk(l2, l3));
}

__global__ void transpose_split_kernel(const float* __restrict__ W,
                                       __nv_bfloat16* __restrict__ outH,
                                       __nv_bfloat16* __restrict__ outL,
                                       int K, int N) {
    __shared__ float tile[32][33];
    int n0 = blockIdx.x * 32, k0 = blockIdx.y * 32;
    int tx = threadIdx.x, ty = threadIdx.y;
#pragma unroll
    for (int i = 0; i < 4; i++) {
        int k = k0 + ty + i * 8;
        int n = n0 + tx;
        tile[ty + i * 8][tx] = (n < N) ? W[(size_t)k * N + n] : 0.f;
    }
    __syncthreads();
#pragma unroll
    for (int i = 0; i < 4; i++) {
        int nrow = n0 + ty + i * 8;
        int kcol = k0 + tx;
        float x = tile[tx][ty + i * 8];
        __nv_bfloat16 h, l;
        split2(x, h, l);
        outH[(size_t)nrow * K + kcol] = h;
        outL[(size_t)nrow * K + kcol] = l;
    }
}

// ================= HMMA split-bf16 GEMM: packed hi/lo rows, 5 stages (R13 order) =================
#define KT      16
#define PITCHB  80
#define PARR_B  (128 * PITCHB)
#define STAGE_B (2 * PARR_B)
#define NSTG    5

extern __shared__ __align__(128) char gsm_raw[];

__global__ void __launch_bounds__(256, 2)
gemm_hmma(const __nv_bfloat16* __restrict__ Ah, const __nv_bfloat16* __restrict__ Al,
          const __nv_bfloat16* __restrict__ Bh, const __nv_bfloat16* __restrict__ Bl,
          float* __restrict__ C, int Nreal, int K) {
    const int tid = threadIdx.x;
    const int lane = tid & 31, wid = tid >> 5;
    const int wm = wid & 1, wn = wid >> 1;
    const int row0 = blockIdx.y * 128, col0 = blockIdx.x * 128;
    const uint32_t sb = smem_u32(gsm_raw);

    const int lrow = tid >> 1;
    const int lelem = (tid & 1) * 8;
    const __nv_bfloat16* pAh = Ah + (size_t)(row0 + lrow) * K + lelem;
    const __nv_bfloat16* pAl = Al + (size_t)(row0 + lrow) * K + lelem;
    const __nv_bfloat16* pBh = Bh + (size_t)(col0 + lrow) * K + lelem;
    const __nv_bfloat16* pBl = Bl + (size_t)(col0 + lrow) * K + lelem;
    const uint32_t dstA = lrow * PITCHB + (tid & 1) * 16;

    float acc[4][4][4];
#pragma unroll
    for (int m = 0; m < 4; m++)
#pragma unroll
        for (int n = 0; n < 4; n++)
#pragma unroll
            for (int v = 0; v < 4; v++) acc[m][n][v] = 0.f;

    const int T = K / KT;

#define GFILL_NC(sidx, ko) do { \
        uint32_t _s = sb + (sidx) * STAGE_B; \
        CP16(_s + dstA,               pAh + (ko)); \
        CP16(_s + dstA + 32,          pAl + (ko)); \
        CP16(_s + PARR_B + dstA,      pBh + (ko)); \
        CP16(_s + PARR_B + dstA + 32, pBl + (ko)); \
    } while (0)

#pragma unroll
    for (int t = 0; t < 4; t++) {
        GFILL_NC(t, t * KT);
        CP_COMMIT();
    }

    const uint32_t a_frag_base = (wm * 64 + (lane & 15)) * PITCHB + (lane >> 4) * 16;
    const uint32_t b_frag_base = (wn * 32 + (lane & 7) + (lane >> 4) * 8) * PITCHB
                                 + ((lane >> 3) & 1) * 16;

    int sread = 0, sfill = 4;
    for (int t = 0; t < T; t++) {
        CP_WAIT(2);
        __syncthreads();
        if (t + 4 < T) GFILL_NC(sfill, (t + 4) * KT);
        CP_COMMIT();

        const uint32_t st = sb + sread * STAGE_B;
        uint32_t bh[2][4], bl[2][4];
#pragma unroll
        for (int np = 0; np < 2; np++) {
            uint32_t bo = st + PARR_B + b_frag_base + np * (16 * PITCHB);
            ldsm_x4(bh[np][0], bh[np][1], bh[np][2], bh[np][3], bo);
            ldsm_x4(bl[np][0], bl[np][1], bl[np][2], bl[np][3], bo + 32);
        }
#pragma unroll
        for (int mt = 0; mt < 4; mt++) {
            uint32_t ah[4], al[4];
            uint32_t ao = st + a_frag_base + mt * (16 * PITCHB);
            ldsm_x4(ah[0], ah[1], ah[2], ah[3], ao);
            ldsm_x4(al[0], al[1], al[2], al[3], ao + 32);
#pragma unroll
            for (int nt = 0; nt < 4; nt++) {
                int np = nt >> 1, hv = (nt & 1) * 2;
                mma16816(acc[mt][nt], ah, bh[np][hv], bh[np][hv + 1]);
                mma16816(acc[mt][nt], ah, bl[np][hv], bl[np][hv + 1]);
                mma16816(acc[mt][nt], al, bh[np][hv], bh[np][hv + 1]);
            }
        }
        sread = (sread + 1 == NSTG) ? 0 : sread + 1;
        sfill = (sfill + 1 == NSTG) ? 0 : sfill + 1;
    }

#pragma unroll
    for (int mt = 0; mt < 4; mt++) {
        int r = row0 + wm * 64 + mt * 16 + (lane >> 2);
#pragma unroll
        for (int nt = 0; nt < 4; nt++) {
            int c = col0 + wn * 32 + nt * 8 + (lane & 3) * 2;
            if (c < Nreal) {
                *(float2*)&C[(size_t)r * Nreal + c]       = make_float2(acc[mt][nt][0], acc[mt][nt][1]);
                *(float2*)&C[(size_t)(r + 8) * Nreal + c] = make_float2(acc[mt][nt][2], acc[mt][nt][3]);
            }
        }
    }
#undef GFILL_NC
}

// ---------------- dt (softplus+clip) and per-chunk cumsum of dt*A ----------------
__global__ void dtcs_kernel(const float* __restrict__ dt_bias, const float* __restrict__ A_log) {
    int c = blockIdx.x, h = blockIdx.y;
    int t = threadIdx.x;
    int Lg = c * CHh + t;
    float raw = g_zx[(size_t)Lg * OUT_IN + DTRAW_OFF + h] + dt_bias[h];
    float sp = (raw > 20.f) ? raw : log1pf(expf(raw));
    float dt = fminf(fmaxf(sp, 0.f), 100.f);
    float A = -expf(A_log[h]);
    __shared__ float s[256];
    s[t] = dt * A;
    __syncthreads();
    for (int off = 1; off < 256; off <<= 1) {
        float v = (t >= off) ? s[t - off] : 0.f;
        __syncthreads();
        s[t] += v;
        __syncthreads();
    }
    int base = (c * Hh + h) * CHh;
    g_dt[base + t] = dt;
    g_acs[base + t] = s[t];
}

// ---------------- fused: causal conv + silu + xdt/BC bf16 split (8 l per block) ----------------
#define CONV_LT 8
__global__ void conv_fused_kernel(const float* __restrict__ cw, const float* __restrict__ cb) {
    int c = blockIdx.x * 256 + threadIdx.x;   // 0..4351
    int l0 = blockIdx.y * CONV_LT;
    float w0 = cw[0 * CONV_DIM + c];
    float w1 = cw[1 * CONV_DIM + c];
    float w2 = cw[2 * CONV_DIM + c];
    float w3 = cw[3 * CONV_DIM + c];
    float bias = cb[c];

    // halo load: rows l0-3 .. l0+CONV_LT-1 for this channel
    float r[CONV_LT + 3];
#pragma unroll
    for (int i = 0; i < CONV_LT + 3; i++) {
        int ll = l0 - 3 + i;
        r[i] = (ll >= 0) ? g_zx[(size_t)ll * OUT_IN + XBC_OFF + c] : 0.f;
    }

    if (c < INTER) {
        int h = c >> 6;
        // l0..l0+7 are within one 256-chunk (l0 is a multiple of 8)
        const float* dtp = &g_dt[((l0 >> 8) * Hh + h) * CHh + (l0 & 255)];
#pragma unroll
        for (int j = 0; j < CONV_LT; j++) {
            float acc = bias;
            acc = fmaf(r[j],     w0, acc);
            acc = fmaf(r[j + 1], w1, acc);
            acc = fmaf(r[j + 2], w2, acc);
            acc = fmaf(r[j + 3], w3, acc);
            float s = acc / (1.f + expf(-acc));
            int l = l0 + j;
            g_x[(size_t)l * INTER + c] = s;
            __nv_bfloat16 hh, ll2;
            split2(s * dtp[j], hh, ll2);
            g_xdth[(size_t)l * INTER + c] = hh;
            g_xdtl[(size_t)l * INTER + c] = ll2;
        }
    } else {
        int cc = c - INTER;
#pragma unroll
        for (int j = 0; j < CONV_LT; j++) {
            float acc = bias;
            acc = fmaf(r[j],     w0, acc);
            acc = fmaf(r[j + 1], w1, acc);
            acc = fmaf(r[j + 2], w2, acc);
            acc = fmaf(r[j + 3], w3, acc);
            float s = acc / (1.f + expf(-acc));
            int l = l0 + j;
            __nv_bfloat16 hh, ll2;
            split2(s, hh, ll2);
            g_bch[(size_t)l * 256 + cc] = hh;
            g_bcl[(size_t)l * 256 + cc] = ll2;
        }
    }
}

// ---------------- HMMA states (cp.async B staging overlapped with X' compute) ----------------
extern __shared__ __align__(128) char ssm2[];
__global__ void __launch_bounds__(128, 2)
states_hmma() {
    const uint32_t sb = smem_u32(ssm2);
    const int tid = threadIdx.x, lane = tid & 31, w = tid >> 5;
    const int c = blockIdx.x, h = blockIdx.y;
    const int base = (c * Hh + h) * CHh;
    const float aend = g_acs[base + 255];
    float* wb = (float*)(ssm2 + 53248);
    for (int t = tid; t < 256; t += 128) wb[t] = expf(aend - g_acs[base + t]);

    float sacc[16][4];
#pragma unroll
    for (int j = 0; j < 16; j++)
#pragma unroll
        for (int v = 0; v < 4; v++) sacc[j][v] = 0.f;

    const uint32_t axb = sb + ((lane & 7) + (lane >> 4) * 8) * 144 + 32 * w + ((lane >> 3) & 1) * 16;
    const uint32_t bxb = sb + 18432 + ((lane & 7) + ((lane >> 3) & 1) * 8) * 272 + (lane >> 4) * 16;

    for (int kt = 0; kt < 4; kt++) {
        __syncthreads();
        int l0 = kt * 64;
        for (int e = tid; e < 1024; e += 128) {
            int row = e >> 4, s = e & 15;
            int lg = c * CHh + l0 + row;
            CP16(sb + 18432 + row * 272 + s * 16, &g_bch[(size_t)lg * 256 + s * 8]);
            CP16(sb + 35840 + row * 272 + s * 16, &g_bcl[(size_t)lg * 256 + s * 8]);
        }
        CP_COMMIT();
        for (int e = tid; e < 2048; e += 128) {
            int row = e >> 5, seg = e & 31;
            int lg = c * CHh + l0 + row;
            __nv_bfloat162 xh2 = *(const __nv_bfloat162*)&g_xdth[(size_t)lg * INTER + h * 64 + seg * 2];
            __nv_bfloat162 xl2 = *(const __nv_bfloat162*)&g_xdtl[(size_t)lg * INTER + h * 64 + seg * 2];
            float wv = wb[l0 + row];
            float v0 = (__bfloat162float(xh2.x) + __bfloat162float(xl2.x)) * wv;
            float v1 = (__bfloat162float(xh2.y) + __bfloat162float(xl2.y)) * wv;
            __nv_bfloat16 a0, a1, b0, b1;
            split2(v0, a0, b0); split2(v1, a1, b1);
            *(uint32_t*)(ssm2 + row * 144 + seg * 4) = pk(a0, a1);
            *(uint32_t*)(ssm2 + 9216 + row * 144 + seg * 4) = pk(b0, b1);
        }
        CP_WAIT(0);
        __syncthreads();

#pragma unroll
        for (int t = 0; t < 4; t++) {
            uint32_t ah[4], al[4];
            ldsm_x4_t(ah[0], ah[1], ah[2], ah[3], axb + t * 2304);
            ldsm_x4_t(al[0], al[1], al[2], al[3], axb + 9216 + t * 2304);
#pragma unroll
            for (int np = 0; np < 8; np++) {
                uint32_t bh[4], bl[4];
                ldsm_x4_t(bh[0], bh[1], bh[2], bh[3], bxb + t * 4352 + np * 32);
                ldsm_x4_t(bl[0], bl[1], bl[2], bl[3], bxb + 17408 + t * 4352 + np * 32);
                mma16816(sacc[2 * np],     ah, bh[0], bh[1]);
                mma16816(sacc[2 * np + 1], ah, bh[2], bh[3]);
                mma16816(sacc[2 * np],     ah, bl[0], bl[1]);
                mma16816(sacc[2 * np + 1], ah, bl[2], bl[3]);
                mma16816(sacc[2 * np],     al, bh[0], bh[1]);
                mma16816(sacc[2 * np + 1], al, bh[2], bh[3]);
            }
        }
    }

    float* out = g_states + (size_t)(c * Hh + h) * 8192;
    int p0 = 16 * w + (lane >> 2);
#pragma unroll
    for (int j = 0; j < 16; j++) {
        int n = 8 * j + 2 * (lane & 3);
        *(float2*)&out[p0 * 128 + n]       = make_float2(sacc[j][0], sacc[j][1]);
        *(float2*)&out[(p0 + 8) * 128 + n] = make_float2(sacc[j][2], sacc[j][3]);
    }
}

// ---------------- inter-chunk state scan (emits split stin) ----------------
__global__ void scan_kernel() {
    int idx = blockIdx.x * 256 + threadIdx.x;
    int h = idx >> 13;
    int rem = idx & 8191;
    float st = 0.f;
    for (int c = 0; c < NC; c++) {
        size_t o = (size_t)(c * Hh + h) * 8192 + rem;
        __nv_bfloat16 hi, lo;
        split2(st, hi, lo);
        g_stinh[o] = hi;
        g_stinl[o] = lo;
        float cend = g_acs[(c * Hh + h) * CHh + 255];
        st = st * expf(cend) + g_states[o];
    }
}

// ---------------- HMMA fused Y kernel: head-paired + overlapped prologue ----------------
#define OFF_CL   17408
#define OFF_UH   34816
#define OFF_UL   52224
#define OFF_X0H  69632
#define OFF_X0L  78848
#define OFF_X1H  88064
#define OFF_X1L  97280
#define OFF_S1H  69632            // Sin_h1 hi (aliases X region during prologue)
#define OFF_S1L  87040            // Sin_h1 lo
#define OFF_AL0  106496
#define OFF_AL1  106752
#define OFF_AS0  107008
#define OFF_AS1  107264
#define YSMEM2   107520
extern __shared__ __align__(128) char ysm2[];
__global__ void __launch_bounds__(128, 2)
y_hmma(const float* __restrict__ Dv) {
    const uint32_t sb = smem_u32(ysm2);
    const int tid = threadIdx.x, lane = tid & 31, w = tid >> 5;
    const int lt = blockIdx.x, c = blockIdx.y, hp = blockIdx.z;
    const int h0 = 2 * hp, h1 = 2 * hp + 1;
    const int base0 = (c * Hh + h0) * CHh;
    const int base1 = (c * Hh + h1) * CHh;
    const int Lrow0 = c * CHh + lt * 64;
    float* acsl0 = (float*)(ysm2 + OFF_AL0);
    float* acsl1 = (float*)(ysm2 + OFF_AL1);
    float* acss0 = (float*)(ysm2 + OFF_AS0);
    float* acss1 = (float*)(ysm2 + OFF_AS1);

    const uint32_t a_base = sb + (16 * w + (lane & 15)) * 272 + (lane >> 4) * 16;
    const uint32_t b_base = sb + OFF_UH + ((lane & 7) + (lane >> 4) * 8) * 272 + ((lane >> 3) & 1) * 16;
    const uint32_t s1_base = sb + OFF_S1H + ((lane & 7) + (lane >> 4) * 8) * 272 + ((lane >> 3) & 1) * 16;
    const uint32_t x0_base = sb + OFF_X0H + ((lane & 7) + ((lane >> 3) & 1) * 8) * 144 + (lane >> 4) * 16;
    const uint32_t x1_base = sb + OFF_X1H + ((lane & 7) + ((lane >> 3) & 1) * 8) * 144 + (lane >> 4) * 16;

    float yacc0[8][4], yacc1[8][4];
#pragma unroll
    for (int j = 0; j < 8; j++)
#pragma unroll
        for (int v = 0; v < 4; v++) { yacc0[j][v] = 0.f; yacc1[j][v] = 0.f; }

    // stage 1: C tile (shared) + Sin_h0 (UH) + Sin_h1 (X region alias) in ONE group
    {
        const size_t sinb0 = (size_t)(c * Hh + h0) * 8192;
        const size_t sinb1 = (size_t)(c * Hh + h1) * 8192;
        for (int e = tid; e < 1024; e += 128) {
            int row = e >> 4, s = e & 15;
            CP16(sb + row * 272 + s * 16,           &g_bch[(size_t)(Lrow0 + row) * 256 + 128 + s * 8]);
            CP16(sb + OFF_CL + row * 272 + s * 16,  &g_bcl[(size_t)(Lrow0 + row) * 256 + 128 + s * 8]);
            CP16(sb + OFF_UH + row * 272 + s * 16,  &g_stinh[sinb0 + row * 128 + s * 8]);
            CP16(sb + OFF_UL + row * 272 + s * 16,  &g_stinl[sinb0 + row * 128 + s * 8]);
            CP16(sb + OFF_S1H + row * 272 + s * 16, &g_stinh[sinb1 + row * 128 + s * 8]);
            CP16(sb + OFF_S1L + row * 272 + s * 16, &g_stinl[sinb1 + row * 128 + s * 8]);
        }
        if (tid < 64) { acsl0[tid] = g_acs[base0 + lt * 64 + tid]; acsl1[tid] = g_acs[base1 + lt * 64 + tid]; }
        CP_COMMIT();
        CP_WAIT(0);
    }
    __syncthreads();

    // Y_off h0 = C . Sin0^T, scaled
#pragma unroll
    for (int kk = 0; kk < 8; kk++) {
        uint32_t ah[4], al[4];
        ldsm_x4(ah[0], ah[1], ah[2], ah[3], a_base + kk * 32);
        ldsm_x4(al[0], al[1], al[2], al[3], a_base + OFF_CL + kk * 32);
#pragma unroll
        for (int np = 0; np < 4; np++) {
            uint32_t bh[4], bl[4];
            ldsm_x4(bh[0], bh[1], bh[2], bh[3], b_base + np * 4352 + kk * 32);
            ldsm_x4(bl[0], bl[1], bl[2], bl[3], b_base + 17408 + np * 4352 + kk * 32);
            mma16816(yacc0[2 * np],     ah, bh[0], bh[1]);
            mma16816(yacc0[2 * np + 1], ah, bh[2], bh[3]);
            mma16816(yacc0[2 * np],     ah, bl[0], bl[1]);
            mma16816(yacc0[2 * np + 1], ah, bl[2], bl[3]);
            mma16816(yacc0[2 * np],     al, bh[0], bh[1]);
            mma16816(yacc0[2 * np + 1], al, bh[2], bh[3]);
        }
    }
    {
        float e0 = expf(acsl0[16 * w + (lane >> 2)]);
        float e1 = expf(acsl0[16 * w + (lane >> 2) + 8]);
#pragma unroll
        for (int j = 0; j < 8; j++) {
            yacc0[j][0] *= e0; yacc0[j][1] *= e0;
            yacc0[j][2] *= e1; yacc0[j][3] *= e1;
        }
    }

    // UH free -> issue B(st=0) now; it streams in while we compute Y_off h1
    __syncthreads();
    {
        const int Srow0 = c * CHh;   // st = 0
        for (int e = tid; e < 1024; e += 128) {
            int row = e >> 4, s = e & 15;
            CP16(sb + OFF_UH + row * 272 + s * 16, &g_bch[(size_t)(Srow0 + row) * 256 + s * 8]);
            CP16(sb + OFF_UL + row * 272 + s * 16, &g_bcl[(size_t)(Srow0 + row) * 256 + s * 8]);
        }
        CP_COMMIT();
    }

    // Y_off h1 = C . Sin1^T (from aliased X region), scaled
#pragma unroll
    for (int kk = 0; kk < 8; kk++) {
        uint32_t ah[4], al[4];
        ldsm_x4(ah[0], ah[1], ah[2], ah[3], a_base + kk * 32);
        ldsm_x4(al[0], al[1], al[2], al[3], a_base + OFF_CL + kk * 32);
#pragma unroll
        for (int np = 0; np < 4; np++) {
            uint32_t bh[4], bl[4];
            ldsm_x4(bh[0], bh[1], bh[2], bh[3], s1_base + np * 4352 + kk * 32);
            ldsm_x4(bl[0], bl[1], bl[2], bl[3], s1_base + (OFF_S1L - OFF_S1H) + np * 4352 + kk * 32);
            mma16816(yacc1[2 * np],     ah, bh[0], bh[1]);
            mma16816(yacc1[2 * np + 1], ah, bh[2], bh[3]);
            mma16816(yacc1[2 * np],     ah, bl[0], bl[1]);
            mma16816(yacc1[2 * np + 1], ah, bl[2], bl[3]);
            mma16816(yacc1[2 * np],     al, bh[0], bh[1]);
            mma16816(yacc1[2 * np + 1], al, bh[2], bh[3]);
        }
    }
    {
        float e0 = expf(acsl1[16 * w + (lane >> 2)]);
        float e1 = expf(acsl1[16 * w + (lane >> 2) + 8]);
#pragma unroll
        for (int j = 0; j < 8; j++) {
            yacc1[j][0] *= e0; yacc1[j][1] *= e0;
            yacc1[j][2] *= e1; yacc1[j][3] *= e1;
        }
    }

    const int l0row = 16 * w + (lane >> 2);

    for (int st = 0; st <= lt; st++) {
        const int Srow0 = c * CHh + st * 64;
        __syncthreads();
        if (st > 0) {   // B(0) already in flight from the prologue
            for (int e = tid; e < 1024; e += 128) {
                int row = e >> 4, s = e & 15;
                CP16(sb + OFF_UH + row * 272 + s * 16, &g_bch[(size_t)(Srow0 + row) * 256 + s * 8]);
                CP16(sb + OFF_UL + row * 272 + s * 16, &g_bcl[(size_t)(Srow0 + row) * 256 + s * 8]);
            }
        }
        for (int e = tid; e < 512; e += 128) {
            int row = e >> 3, s = e & 7;
            CP16(sb + OFF_X0H + row * 144 + s * 16, &g_xdth[(size_t)(Srow0 + row) * INTER + h0 * 64 + s * 8]);
            CP16(sb + OFF_X0L + row * 144 + s * 16, &g_xdtl[(size_t)(Srow0 + row) * INTER + h0 * 64 + s * 8]);
            CP16(sb + OFF_X1H + row * 144 + s * 16, &g_xdth[(size_t)(Srow0 + row) * INTER + h1 * 64 + s * 8]);
            CP16(sb + OFF_X1L + row * 144 + s * 16, &g_xdtl[(size_t)(Srow0 + row) * INTER + h1 * 64 + s * 8]);
        }
        if (tid < 64) { acss0[tid] = g_acs[base0 + st * 64 + tid]; acss1[tid] = g_acs[base1 + st * 64 + tid]; }
        CP_COMMIT();
        CP_WAIT(0);
        __syncthreads();

        // raw G = C . B^T (shared across both heads)
        float gacc[8][4];
#pragma unroll
        for (int j = 0; j < 8; j++)
#pragma unroll
            for (int v = 0; v < 4; v++) gacc[j][v] = 0.f;
#pragma unroll
        for (int kk = 0; kk < 8; kk++) {
            uint32_t ah[4], al[4];
            ldsm_x4(ah[0], ah[1], ah[2], ah[3], a_base + kk * 32);
            ldsm_x4(al[0], al[1], al[2], al[3], a_base + OFF_CL + kk * 32);
#pragma unroll
            for (int np = 0; np < 4; np++) {
                uint32_t bh[4], bl[4];
                ldsm_x4(bh[0], bh[1], bh[2], bh[3], b_base + np * 4352 + kk * 32);
                ldsm_x4(bl[0], bl[1], bl[2], bl[3], b_base + 17408 + np * 4352 + kk * 32);
                mma16816(gacc[2 * np],     ah, bh[0], bh[1]);
                mma16816(gacc[2 * np + 1], ah, bh[2], bh[3]);
                mma16816(gacc[2 * np],     ah, bl[0], bl[1]);
                mma16816(gacc[2 * np + 1], ah, bl[2], bl[3]);
                mma16816(gacc[2 * np],     al, bh[0], bh[1]);
                mma16816(gacc[2 * np + 1], al, bh[2], bh[3]);
            }
        }

        const bool diag = (st == lt);
#pragma unroll
        for (int hh = 0; hh < 2; hh++) {
            const float* acslh = hh ? acsl1 : acsl0;
            const float* acssh = hh ? acss1 : acss0;
            const uint32_t xb = hh ? x1_base : x0_base;
            float (*yh)[4] = hh ? yacc1 : yacc0;
            float rA = acslh[l0row];
            float rB = acslh[l0row + 8];
#pragma unroll
            for (int t = 0; t < 4; t++) {
                uint32_t gah[4], gal[4];
#pragma unroll
                for (int half = 0; half < 2; half++) {
                    int j = 2 * t + half;
                    int s0 = 8 * j + 2 * (lane & 3);
                    float c0 = acssh[s0], c1 = acssh[s0 + 1];
                    float e00 = expf(rA - c0), e01 = expf(rA - c1);
                    float e10 = expf(rB - c0), e11 = expf(rB - c1);
                    if (diag) {
                        if (s0 > l0row)         e00 = 0.f;
                        if (s0 + 1 > l0row)     e01 = 0.f;
                        if (s0 > l0row + 8)     e10 = 0.f;
                        if (s0 + 1 > l0row + 8) e11 = 0.f;
                    }
                    float v0 = gacc[j][0] * e00, v1 = gacc[j][1] * e01;
                    float v2 = gacc[j][2] * e10, v3 = gacc[j][3] * e11;
                    __nv_bfloat16 p0, p1, p2, p3, q0, q1, q2, q3;
                    split2(v0, p0, q0); split2(v1, p1, q1);
                    split2(v2, p2, q2); split2(v3, p3, q3);
                    gah[2 * half]     = pk(p0, p1);
                    gah[2 * half + 1] = pk(p2, p3);
                    gal[2 * half]     = pk(q0, q1);
                    gal[2 * half + 1] = pk(q2, q3);
                }
#pragma unroll
                for (int np = 0; np < 4; np++) {
                    uint32_t xh[4], xl[4];
                    ldsm_x4_t(xh[0], xh[1], xh[2], xh[3], xb + t * 2304 + np * 32);
                    ldsm_x4_t(xl[0], xl[1], xl[2], xl[3], xb + 9216 + t * 2304 + np * 32);
                    mma16816(yh[2 * np],     gah, xh[0], xh[1]);
                    mma16816(yh[2 * np + 1], gah, xh[2], xh[3]);
                    mma16816(yh[2 * np],     gah, xl[0], xl[1]);
                    mma16816(yh[2 * np + 1], gah, xl[2], xl[3]);
                    mma16816(yh[2 * np],     gal, xh[0], xh[1]);
                    mma16816(yh[2 * np + 1], gal, xh[2], xh[3]);
                }
            }
        }
    }

    // epilogue: + x*D, write g_y for both heads
    int r0 = Lrow0 + l0row;
#pragma unroll
    for (int hh = 0; hh < 2; hh++) {
        int h = hh ? h1 : h0;
        float dh = Dv[h];
        float (*yh)[4] = hh ? yacc1 : yacc0;
#pragma unroll
        for (int j = 0; j < 8; j++) {
            int p = h * 64 + 8 * j + 2 * (lane & 3);
            float2 x0 = *(const float2*)&g_x[(size_t)r0 * INTER + p];
            float2 x1 = *(const float2*)&g_x[(size_t)(r0 + 8) * INTER + p];
            *(float2*)&g_y[(size_t)r0 * INTER + p] =
                make_float2(yh[j][0] + x0.x * dh, yh[j][1] + x0.y * dh);
            *(float2*)&g_y[(size_t)(r0 + 8) * INTER + p] =
                make_float2(yh[j][2] + x1.x * dh, yh[j][3] + x1.y * dh);
        }
    }
}

// ---------------- gated RMSNorm fused with bf16 hi/lo split ----------------
__global__ void rmsnorm_split_kernel(const float* __restrict__ nw) {
    int l = blockIdx.x;
    int tid = threadIdx.x;
    float v[16];
    float ss = 0.f;
#pragma unroll
    for (int i = 0; i < 16; i++) {
        int col = tid + i * 256;
        float y = g_y[(size_t)l * INTER + col];
        float z = g_zx[(size_t)l * OUT_IN + col];
        float yf = y * (z / (1.f + expf(-z)));
        v[i] = yf;
        ss = fmaf(yf, yf, ss);
    }
    __shared__ float red[256];
    red[tid] = ss;
    __syncthreads();
    for (int o = 128; o > 0; o >>= 1) {
        if (tid < o) red[tid] += red[tid + o];
        __syncthreads();
    }
    float scale = rsqrtf(red[0] / (float)INTER + 1e-5f);
#pragma unroll
    for (int i = 0; i < 16; i++) {
        int col = tid + i * 256;
        float yn = v[i] * scale * nw[col];
        __nv_bfloat16 h, lo;
        split2(yn, h, lo);
        gA2h[(size_t)l * INTER + col] = h;
        gA2l[(size_t)l * INTER + col] = lo;
    }
}

// ---------------- launch ----------------
extern "C" void kernel_launch(void* const* d_in, const int* in_sizes, int n_in,
                              void* d_out, int out_size) {
    const float* hs      = (const float*)d_in[0];
    const float* W_in    = (const float*)d_in[1];
    const float* conv_w  = (const float*)d_in[2];
    const float* conv_b  = (const float*)d_in[3];
    const float* dt_bias = (const float*)d_in[4];
    const float* A_log   = (const float*)d_in[5];
    const float* Dv      = (const float*)d_in[6];
    const float* norm_w  = (const float*)d_in[7];
    const float* W_out   = (const float*)d_in[8];
    float* out = (float*)d_out;

    void *p_zx;
    void *pA1h, *pA1l, *pB1h, *pB1l, *pA2h, *pA2l, *pB2h, *pB2l;
    cudaGetSymbolAddress(&p_zx, g_zx);
    cudaGetSymbolAddress(&pA1h, gA1h); cudaGetSymbolAddress(&pA1l, gA1l);
    cudaGetSymbolAddress(&pB1h, gB1h); cudaGetSymbolAddress(&pB1l, gB1l);
    cudaGetSymbolAddress(&pA2h, gA2h); cudaGetSymbolAddress(&pA2l, gA2l);
    cudaGetSymbolAddress(&pB2h, gB2h); cudaGetSymbolAddress(&pB2l, gB2l);

    const int GSMEM = NSTG * STAGE_B;   // 102400 -> 2 CTAs/SM
    cudaFuncSetAttribute(gemm_hmma, cudaFuncAttributeMaxDynamicSharedMemorySize, GSMEM);
    cudaFuncSetAttribute(y_hmma, cudaFuncAttributeMaxDynamicSharedMemorySize, YSMEM2);
    cudaFuncSetAttribute(states_hmma, cudaFuncAttributeMaxDynamicSharedMemorySize, 54272);

    // 1) split hs -> A1
    split_kernel<<<(L_ * HIDD / 4 + 255) / 256, 256>>>(hs, (__nv_bfloat16*)pA1h, (__nv_bfloat16*)pA1l, L_ * HIDD / 4);
    // 2) transpose+split W_in -> B1
    transpose_split_kernel<<<dim3(OUT_IN_PAD / 32, HIDD / 32), dim3(32, 8)>>>(
        W_in, (__nv_bfloat16*)pB1h, (__nv_bfloat16*)pB1l, HIDD, OUT_IN);
    // 3) transpose+split W_out -> B2
    transpose_split_kernel<<<dim3(HIDD / 32, INTER / 32), dim3(32, 8)>>>(
        W_out, (__nv_bfloat16*)pB2h, (__nv_bfloat16*)pB2l, INTER, HIDD);
    // 4) zxbcdt = hs @ W_in   <-- profiled launch
    gemm_hmma<<<dim3(OUT_IN_PAD / 128, L_ / 128), 256, GSMEM>>>(
        (const __nv_bfloat16*)pA1h, (const __nv_bfloat16*)pA1l,
        (const __nv_bfloat16*)pB1h, (const __nv_bfloat16*)pB1l,
        (float*)p_zx, OUT_IN, HIDD);
    // 5) dt + per-chunk cumsum
    dtcs_kernel<<<dim3(NC, Hh), 256>>>(dt_bias, A_log);
    // 6) fused conv + silu + xdt/BC splits (8 l per block, halo reuse)
    conv_fused_kernel<<<dim3(CONV_DIM / 256, L_ / CONV_LT), 256>>>(conv_w, conv_b);
    // 7) per-chunk states (HMMA)
    states_hmma<<<dim3(NC, Hh), 128, 54272>>>();
    // 8) inter-chunk scan
    scan_kernel<<<(Hh * Pp * Nn) / 256, 256>>>();
    // 9) Y (HMMA, head-paired, overlapped prologue)
    y_hmma<<<dim3(4, NC, Hh / 2), 128, YSMEM2>>>(Dv);
    // 10) gated RMSNorm + split A2
    rmsnorm_split_kernel<<<L_, 256>>>(norm_w);
    // 11) out = yn @ W_out
    gemm_hmma<<<dim3(HIDD / 128, L_ / 128), 256, GSMEM>>>(
        (const __nv_bfloat16*)pA2h, (const __nv_bfloat16*)pA2l,
        (const __nv_bfloat16*)pB2h, (const __nv_bfloat16*)pB2l,
        out, HIDD, INTER);
}